// round 6
// baseline (speedup 1.0000x reference)
#include <cuda_runtime.h>
#include <math.h>

// ---------------- problem constants ----------------
// B=1, H=W=64, Q=4096, DIM=256, HEAD=8, R=3, RA=49
#define NPIX 4096
#define NQ   4096
#define KPAD 12560   // 12546 padded up (mult of 16)

// ---------------- scratch (device globals; no allocations) ----------------
__device__ float g_enc [64  * NPIX];          // NCHW  64x64x64
__device__ float g_feat[256 * NPIX];          // NCHW 256x64x64
__device__ float g_fq  [NPIX * 256];          // NHWC
__device__ float g_fk  [NPIX * 256];          // NHWC
__device__ float g_fv  [NPIX * 256];          // NHWC
__device__ float g_o   [NPIX * 256];          // NHWC (grouped conv out)
__device__ float g_actv[NPIX * 256];          // NHWC (LN+GELU out)
__device__ float g_offs[NPIX * 98];           // NHWC
__device__ float g_Wc1T[98 * 256];            // transposed Wc1
__device__ float g_Wi1p[256 * KPAD];          // zero-padded Wi1
__device__ float g_featin[(size_t)NQ * KPAD]; // 196 MB
__device__ float g_hidden[NQ * 256];
__device__ float g_skip [NQ * 3];

// ---------------- conv1: 3->64, 3x3, pad1, ReLU (naive, tiny) ----------------
__global__ void conv_enc_kernel(const float* __restrict__ inp,
                                const float* __restrict__ w,
                                const float* __restrict__ b) {
    int idx = blockIdx.x * 256 + threadIdx.x;
    if (idx >= 64 * NPIX) return;
    int oc  = idx >> 12;
    int pix = idx & 4095;
    int y = pix >> 6, x = pix & 63;
    float acc = b[oc];
    #pragma unroll
    for (int ic = 0; ic < 3; ic++) {
        #pragma unroll
        for (int dy = 0; dy < 3; dy++) {
            int yy = y + dy - 1;
            if (yy < 0 || yy > 63) continue;
            #pragma unroll
            for (int dx = 0; dx < 3; dx++) {
                int xx = x + dx - 1;
                if (xx < 0 || xx > 63) continue;
                acc += inp[ic * NPIX + yy * 64 + xx] * w[(oc * 3 + ic) * 9 + dy * 3 + dx];
            }
        }
    }
    g_enc[idx] = fmaxf(acc, 0.f);
}

// ---------------- tiled 3x3 conv body: 128 thr, tile 32x16, 16 oc, 4 px/thr --
template<int CIN, bool NHWC>
__device__ __forceinline__ void conv3x3_body(const float* __restrict__ in,
                                             const float* __restrict__ w,
                                             const float* __restrict__ bias,
                                             float* __restrict__ out) {
    __shared__ float sIn[4][18][36];
    __shared__ float sW[576];       // 16 oc x 4 ic x 9
    const int tid = threadIdx.x;
    const int tile = blockIdx.x;               // 8 tiles: 2 x-tiles * 4 y-tiles
    const int x0 = (tile & 1) * 32;
    const int y0 = (tile >> 1) * 16;
    const int oc0 = blockIdx.y * 16;
    const int tx = (tid & 7) * 4;
    const int ty = tid >> 3;

    float acc[16][4];
    #pragma unroll
    for (int i = 0; i < 16; i++)
        #pragma unroll
        for (int p = 0; p < 4; p++) acc[i][p] = 0.f;

    for (int icb = 0; icb < CIN; icb += 4) {
        // weights: 16 oc * 36 consecutive floats each
        for (int idx = tid; idx < 576; idx += 128) {
            int oc = idx / 36, r = idx % 36;
            sW[idx] = w[((size_t)(oc0 + oc) * CIN + icb) * 9 + r];
        }
        // input patch 4 x 18 x 34
        for (int idx = tid; idx < 4 * 18 * 34; idx += 128) {
            int ic = idx / (18 * 34);
            int rem = idx % (18 * 34);
            int row = rem / 34, col = rem % 34;
            int gy = y0 + row - 1, gx = x0 + col - 1;
            float v = 0.f;
            if (gy >= 0 && gy < 64 && gx >= 0 && gx < 64)
                v = in[(icb + ic) * NPIX + gy * 64 + gx];
            sIn[ic][row][col] = v;
        }
        __syncthreads();
        #pragma unroll
        for (int ic = 0; ic < 4; ic++) {
            float r_[3][6];
            #pragma unroll
            for (int ry = 0; ry < 3; ry++)
                #pragma unroll
                for (int cx = 0; cx < 6; cx++)
                    r_[ry][cx] = sIn[ic][ty + ry][tx + cx];
            #pragma unroll
            for (int oc = 0; oc < 16; oc++) {
                #pragma unroll
                for (int qf = 0; qf < 9; qf++) {
                    float wv = sW[oc * 36 + ic * 9 + qf];
                    int dy = qf / 3, dx = qf % 3;
                    #pragma unroll
                    for (int p = 0; p < 4; p++)
                        acc[oc][p] += wv * r_[dy][p + dx];
                }
            }
        }
        __syncthreads();
    }
    #pragma unroll
    for (int oc = 0; oc < 16; oc++) {
        float bb = bias[oc0 + oc];
        #pragma unroll
        for (int p = 0; p < 4; p++) {
            float v = acc[oc][p] + bb;
            int y = y0 + ty, x = x0 + tx + p;
            if (NHWC) out[(y * 64 + x) * 256 + oc0 + oc] = v;
            else      out[(oc0 + oc) * NPIX + y * 64 + x] = v;
        }
    }
}

__global__ void conv_ch_kernel(const float* __restrict__ w, const float* __restrict__ b) {
    conv3x3_body<64, false>(g_enc, w, b, g_feat);
}

__global__ void conv_qkv_kernel(const float* __restrict__ wq, const float* __restrict__ bq,
                                const float* __restrict__ wk, const float* __restrict__ bk,
                                const float* __restrict__ wv, const float* __restrict__ bv) {
    const float* w; const float* b; float* out;
    if (blockIdx.z == 0)      { w = wq; b = bq; out = g_fq; }
    else if (blockIdx.z == 1) { w = wk; b = bk; out = g_fk; }
    else                      { w = wv; b = bv; out = g_fv; }
    conv3x3_body<256, true>(g_feat, w, b, out);
}

// ---------------- grouped 5x5 conv (8 groups of 32->32), pad2 --------------
__global__ void conv_off1_kernel(const float* __restrict__ w, const float* __restrict__ bias) {
    const int g = blockIdx.y;
    const int tile = blockIdx.x;            // 16 tiles of 16x16
    const int x0 = (tile & 3) * 16, y0 = (tile >> 2) * 16;
    const int tid = threadIdx.x;
    const int lx = tid & 15, ly = tid >> 4;
    const int x = x0 + lx, y = y0 + ly;
    __shared__ float sIn[20][20];
    __shared__ float sW[800];
    float acc[32];
    #pragma unroll
    for (int i = 0; i < 32; i++) acc[i] = 0.f;

    for (int ic = 0; ic < 32; ic++) {
        for (int idx = tid; idx < 400; idx += 256) {
            int row = idx / 20, col = idx % 20;
            int gy = y0 + row - 2, gx = x0 + col - 2;
            float v = 0.f;
            if (gy >= 0 && gy < 64 && gx >= 0 && gx < 64)
                v = g_feat[(g * 32 + ic) * NPIX + gy * 64 + gx];
            sIn[row][col] = v;
        }
        for (int idx = tid; idx < 800; idx += 256) {
            int oc = idx / 25, p = idx % 25;
            sW[idx] = w[((g * 32 + oc) * 32 + ic) * 25 + p];
        }
        __syncthreads();
        float r[25];
        #pragma unroll
        for (int p = 0; p < 25; p++) r[p] = sIn[ly + p / 5][lx + p % 5];
        #pragma unroll
        for (int oc = 0; oc < 32; oc++) {
            float a = acc[oc];
            #pragma unroll
            for (int p = 0; p < 25; p++) a += sW[oc * 25 + p] * r[p];
            acc[oc] = a;
        }
        __syncthreads();
    }
    #pragma unroll
    for (int oc = 0; oc < 32; oc++)
        g_o[(y * 64 + x) * 256 + g * 32 + oc] = acc[oc] + bias[g * 32 + oc];
}

// ---------------- LayerNorm(256 ch) + exact GELU ---------------------------
__global__ void ln_gelu_kernel(const float* __restrict__ lng, const float* __restrict__ lnb) {
    const int pix = blockIdx.x;
    const int c = threadIdx.x;
    float x = g_o[pix * 256 + c];
    __shared__ float red[256];
    __shared__ float s_mu, s_var;
    red[c] = x; __syncthreads();
    for (int s = 128; s > 0; s >>= 1) { if (c < s) red[c] += red[c + s]; __syncthreads(); }
    if (c == 0) s_mu = red[0] / 256.f;
    __syncthreads();
    float d = x - s_mu;
    red[c] = d * d; __syncthreads();
    for (int s = 128; s > 0; s >>= 1) { if (c < s) red[c] += red[c + s]; __syncthreads(); }
    if (c == 0) s_var = red[0] / 256.f;
    __syncthreads();
    float xn = d / sqrtf(s_var + 1e-5f) * lng[c] + lnb[c];
    float ge = 0.5f * xn * (1.0f + erff(xn * 0.7071067811865475f));
    g_actv[pix * 256 + c] = ge;
}

// ---------------- 1x1 conv 256->98, no bias --------------------------------
__global__ void conv_off2_kernel(const float* __restrict__ w) {
    const int pix = blockIdx.x;
    const int tid = threadIdx.x; // 128
    __shared__ float sx[256];
    sx[tid] = g_actv[pix * 256 + tid];
    sx[tid + 128] = g_actv[pix * 256 + tid + 128];
    __syncthreads();
    if (tid < 98) {
        float a = 0.f;
        #pragma unroll 8
        for (int c = 0; c < 256; c++) a += w[tid * 256 + c] * sx[c];
        g_offs[pix * 98 + tid] = a;
    }
}

// ---------------- weight prep ----------------------------------------------
__global__ void transpose_wc1_kernel(const float* __restrict__ Wc1) {
    int idx = blockIdx.x * 256 + threadIdx.x;
    if (idx >= 98 * 256) return;
    int j = idx / 256, c = idx % 256;
    g_Wc1T[idx] = Wc1[c * 98 + j];
}
__global__ void pad_wi1_kernel(const float* __restrict__ Wi1) {
    int idx = blockIdx.x * 256 + threadIdx.x;
    if (idx >= 256 * KPAD) return;
    int n = idx / KPAD, k = idx % KPAD;
    g_Wi1p[idx] = (k < 12546) ? Wi1[n * 12546 + k] : 0.f;
}

// ---------------- per-query deformable attention ---------------------------
__global__ void query_kernel(const float* __restrict__ coord,
                             const float* __restrict__ cell,
                             const float* __restrict__ inp,
                             const float* __restrict__ bc1,
                             const float* __restrict__ Wc2,
                             const float* __restrict__ bc2) {
    const int q = blockIdx.x;
    const int tid = threadIdx.x;     // 256
    const int lane = tid & 31;
    const int head = tid >> 5;

    __shared__ int   s_pix[49];
    __shared__ float s_mask[49];
    __shared__ float s_rel[98];
    __shared__ float s_logit[49 * 8];
    __shared__ float s_hid[256];
    __shared__ float s_wc[49];

    const float cy = coord[2 * q], cx = coord[2 * q + 1];
    const float gqx = ((cx + 1.f) * 64.f - 1.f) * 0.5f;
    const float gqy = ((cy + 1.f) * 64.f - 1.f) * 0.5f;
    // nearest base (coord_lr + offsets sampling)
    const float rx = rintf(gqx), ry = rintf(gqy);
    const bool m0 = (rx >= 0.f) && (rx < 64.f) && (ry >= 0.f) && (ry < 64.f);
    const float m0f = m0 ? 1.f : 0.f;
    const int ixq = min(max((int)rx, 0), 63);
    const int iyq = min(max((int)ry, 0), 63);
    const float sck_y = m0f * (-1.f + 1.f / 64.f + (2.f / 64.f) * (float)iyq);
    const float sck_x = m0f * (-1.f + 1.f / 64.f + (2.f / 64.f) * (float)ixq);

    if (tid < 49) {
        int k = tid;
        float o0 = g_offs[(iyq * 64 + ixq) * 98 + 2 * k]     * m0f;
        float o1 = g_offs[(iyq * 64 + ixq) * 98 + 2 * k + 1] * m0f;
        float offy = tanhf(o0) * (2.f / 63.f);
        float offx = tanhf(o1) * (2.f / 63.f);
        float dy = (float)(k / 7 - 3) * (2.f / 64.f);
        float dx = (float)(k % 7 - 3) * (2.f / 64.f);
        float py = sck_y + dy + offy;
        float px = sck_x + dx + offx;
        float gxk = ((px + 1.f) * 64.f - 1.f) * 0.5f;
        float gyk = ((py + 1.f) * 64.f - 1.f) * 0.5f;
        float rxk = rintf(gxk), ryk = rintf(gyk);
        bool mk = (rxk >= 0.f) && (rxk < 64.f) && (ryk >= 0.f) && (ryk < 64.f);
        s_pix[k]  = min(max((int)ryk, 0), 63) * 64 + min(max((int)rxk, 0), 63);
        s_mask[k] = mk ? 1.f : 0.f;
        s_rel[2 * k]     = (cy - py) * 64.f;
        s_rel[2 * k + 1] = (cx - px) * 64.f;
    }
    __syncthreads();

    // q: bilinear zeros-padding sample of fq (per channel = tid)
    float x0f = floorf(gqx), y0f = floorf(gqy);
    float wx = gqx - x0f, wy = gqy - y0f;
    int x0 = (int)x0f, y0 = (int)y0f;
    float qv = 0.f;
    #pragma unroll
    for (int dyc = 0; dyc < 2; dyc++) {
        #pragma unroll
        for (int dxc = 0; dxc < 2; dxc++) {
            int xi = x0 + dxc, yi = y0 + dyc;
            float wgt = (dxc ? wx : 1.f - wx) * (dyc ? wy : 1.f - wy);
            if (xi >= 0 && xi < 64 && yi >= 0 && yi < 64)
                qv += wgt * g_fq[(yi * 64 + xi) * 256 + tid];
        }
    }

    // attention logits: per sample, per head dot over 32 dims (warp==head)
    for (int k = 0; k < 49; k++) {
        float kv = s_mask[k] * g_fk[s_pix[k] * 256 + tid];
        float p = qv * kv;
        p += __shfl_xor_sync(0xffffffffu, p, 16);
        p += __shfl_xor_sync(0xffffffffu, p, 8);
        p += __shfl_xor_sync(0xffffffffu, p, 4);
        p += __shfl_xor_sync(0xffffffffu, p, 2);
        p += __shfl_xor_sync(0xffffffffu, p, 1);
        if (lane == 0) s_logit[k * 8 + head] = p * 0.17677669529663687f;
    }
    __syncthreads();

    // wcoord MLP: 98 -> 256 (relu) -> 49
    {
        float h = bc1[tid];
        #pragma unroll 7
        for (int j = 0; j < 98; j++) h += g_Wc1T[j * 256 + tid] * s_rel[j];
        s_hid[tid] = fmaxf(h, 0.f);
    }
    __syncthreads();
    if (tid < 49) {
        float a = bc2[tid];
        #pragma unroll 8
        for (int c = 0; c < 256; c++) a += Wc2[tid * 256 + c] * s_hid[c];
        s_wc[tid] = a;
    }
    __syncthreads();

    // softmax over k per head
    if (tid < 8) {
        int hh = tid;
        float mx = -1e30f;
        for (int k = 0; k < 49; k++) {
            float t = s_wc[k] + s_logit[k * 8 + hh];
            if (t > mx) mx = t;
        }
        float sum = 0.f;
        for (int k = 0; k < 49; k++) {
            float e = expf(s_wc[k] + s_logit[k * 8 + hh] - mx);
            s_logit[k * 8 + hh] = e;
            sum += e;
        }
        float inv = 1.f / sum;
        for (int k = 0; k < 49; k++) s_logit[k * 8 + hh] *= inv;
    }
    __syncthreads();

    // feat_in = v * attn   (NHWC gather of fv, coalesced)
    size_t base = (size_t)q * KPAD;
    for (int k = 0; k < 49; k++) {
        float v = s_mask[k] * g_fv[s_pix[k] * 256 + tid];
        g_featin[base + k * 256 + tid] = v * s_logit[k * 8 + head];
    }
    if (tid < 16) {
        float val = 0.f;
        if (tid == 0) val = cell[2 * q] * 64.f;
        else if (tid == 1) val = cell[2 * q + 1] * 64.f;
        g_featin[base + 12544 + tid] = val;
    }

    // skip: bilinear border sample of inp
    if (tid < 3) {
        float gxc = fminf(fmaxf(gqx, 0.f), 63.f);
        float gyc = fminf(fmaxf(gqy, 0.f), 63.f);
        float xf = floorf(gxc), yf = floorf(gyc);
        float bx = gxc - xf, by = gyc - yf;
        int xa = (int)xf, ya = (int)yf;
        int xb = min(xa + 1, 63), yb = min(ya + 1, 63);
        const float* ch = inp + tid * NPIX;
        float s = (1.f - bx) * (1.f - by) * ch[ya * 64 + xa]
                +        bx  * (1.f - by) * ch[ya * 64 + xb]
                + (1.f - bx) *        by  * ch[yb * 64 + xa]
                +        bx  *        by  * ch[yb * 64 + xb];
        g_skip[q * 3 + tid] = s;
    }
}

// ---------------- GEMM: hidden = relu(feat_in @ Wi1p^T + b) ---------------
// M=4096, N=256, K=12560; BM=BN=64, BK=16, 256 thr, 4x4 micro-tile
__global__ void gemm_relu_kernel(const float* __restrict__ bi1) {
    __shared__ float As[16][68];
    __shared__ float Bs[16][68];
    const int tid = threadIdx.x;
    const int bm = blockIdx.x * 64;
    const int bn = blockIdx.y * 64;
    const int tn = (tid % 16) * 4;
    const int tm = (tid / 16) * 4;
    const int arow = tid >> 2;
    const int akc = (tid & 3) * 4;

    float acc[4][4];
    #pragma unroll
    for (int i = 0; i < 4; i++)
        #pragma unroll
        for (int j = 0; j < 4; j++) acc[i][j] = 0.f;

    for (int k0 = 0; k0 < KPAD; k0 += 16) {
        float4 a = *(const float4*)&g_featin[(size_t)(bm + arow) * KPAD + k0 + akc];
        float4 b = *(const float4*)&g_Wi1p[(size_t)(bn + arow) * KPAD + k0 + akc];
        As[akc + 0][arow] = a.x; As[akc + 1][arow] = a.y;
        As[akc + 2][arow] = a.z; As[akc + 3][arow] = a.w;
        Bs[akc + 0][arow] = b.x; Bs[akc + 1][arow] = b.y;
        Bs[akc + 2][arow] = b.z; Bs[akc + 3][arow] = b.w;
        __syncthreads();
        #pragma unroll
        for (int kk = 0; kk < 16; kk++) {
            float4 av = *(const float4*)&As[kk][tm];
            float4 bv = *(const float4*)&Bs[kk][tn];
            float am[4] = {av.x, av.y, av.z, av.w};
            float bn_[4] = {bv.x, bv.y, bv.z, bv.w};
            #pragma unroll
            for (int i = 0; i < 4; i++)
                #pragma unroll
                for (int j = 0; j < 4; j++)
                    acc[i][j] += am[i] * bn_[j];
        }
        __syncthreads();
    }
    #pragma unroll
    for (int i = 0; i < 4; i++) {
        int m = bm + tm + i;
        #pragma unroll
        for (int j = 0; j < 4; j++) {
            int n = bn + tn + j;
            g_hidden[m * 256 + n] = fmaxf(acc[i][j] + bi1[n], 0.f);
        }
    }
}

// ---------------- final: pred = Wi2 @ hidden + bi2 + skip ------------------
__global__ void final_kernel(const float* __restrict__ Wi2,
                             const float* __restrict__ bi2,
                             float* __restrict__ out) {
    int idx = blockIdx.x * 128 + threadIdx.x;
    if (idx >= NQ * 3) return;
    int q = idx / 3, o = idx % 3;
    float acc = bi2[o];
    const float* h = g_hidden + q * 256;
    const float* w = Wi2 + o * 256;
    #pragma unroll 8
    for (int c = 0; c < 256; c++) acc += w[c] * h[c];
    out[idx] = acc + g_skip[idx];
}

// ---------------- launcher -------------------------------------------------
extern "C" void kernel_launch(void* const* d_in, const int* in_sizes, int n_in,
                              void* d_out, int out_size) {
    const float* inp    = (const float*)d_in[0];
    const float* coord  = (const float*)d_in[1];
    const float* cell   = (const float*)d_in[2];
    const float* W_enc  = (const float*)d_in[3];
    const float* b_enc  = (const float*)d_in[4];
    const float* W_ch   = (const float*)d_in[5];
    const float* b_ch   = (const float*)d_in[6];
    const float* W_q    = (const float*)d_in[7];
    const float* b_q    = (const float*)d_in[8];
    const float* W_k    = (const float*)d_in[9];
    const float* b_k    = (const float*)d_in[10];
    const float* W_v    = (const float*)d_in[11];
    const float* b_v    = (const float*)d_in[12];
    const float* W_off1 = (const float*)d_in[13];
    const float* b_off1 = (const float*)d_in[14];
    const float* ln_g   = (const float*)d_in[15];
    const float* ln_b   = (const float*)d_in[16];
    const float* W_off2 = (const float*)d_in[17];
    const float* Wc1    = (const float*)d_in[18];
    const float* bc1    = (const float*)d_in[19];
    const float* Wc2    = (const float*)d_in[20];
    const float* bc2    = (const float*)d_in[21];
    const float* Wi1    = (const float*)d_in[22];
    const float* bi1    = (const float*)d_in[23];
    const float* Wi2    = (const float*)d_in[24];
    const float* bi2    = (const float*)d_in[25];
    float* out = (float*)d_out;

    conv_enc_kernel<<<(64 * NPIX + 255) / 256, 256>>>(inp, W_enc, b_enc);
    conv_ch_kernel<<<dim3(8, 16), 128>>>(W_ch, b_ch);
    conv_qkv_kernel<<<dim3(8, 16, 3), 128>>>(W_q, b_q, W_k, b_k, W_v, b_v);
    conv_off1_kernel<<<dim3(16, 8), 256>>>(W_off1, b_off1);
    ln_gelu_kernel<<<NPIX, 256>>>(ln_g, ln_b);
    conv_off2_kernel<<<NPIX, 128>>>(W_off2);
    transpose_wc1_kernel<<<(98 * 256 + 255) / 256, 256>>>(Wc1);
    pad_wi1_kernel<<<(256 * KPAD + 255) / 256, 256>>>(Wi1);
    query_kernel<<<NQ, 256>>>(coord, cell, inp, bc1, Wc2, bc2);
    gemm_relu_kernel<<<dim3(64, 4), 256>>>(bi1);
    final_kernel<<<(NQ * 3 + 127) / 128, 128>>>(Wi2, bi2, out);
}

// round 11
// speedup vs baseline: 1.4390x; 1.4390x over previous
#include <cuda_runtime.h>
#include <cuda_bf16.h>
#include <stdint.h>
#include <math.h>

// ---------------- problem constants ----------------
// B=1, H=W=64, Q=4096, DIM=256, HEAD=8, R=3, RA=49
#define NPIX 4096
#define NQ   4096
#define KP   12576   // 12546 padded up to 32*393

// ---------------- scratch (device globals; no allocations) ----------------
__device__ float g_enc [64  * NPIX];          // NCHW  64x64x64
__device__ float g_feat[256 * NPIX];          // NCHW 256x64x64
__device__ float g_fq  [NPIX * 256];          // NHWC
__device__ float g_fk  [NPIX * 256];          // NHWC
__device__ float g_fv  [NPIX * 256];          // NHWC
__device__ float g_o   [NPIX * 256];          // NHWC (grouped conv out)
__device__ float g_actv[NPIX * 256];          // NHWC (LN+GELU out)
__device__ float g_offs[NPIX * 98];           // NHWC
__device__ float g_Wc1T[98 * 256];            // transposed Wc1
__device__ __nv_bfloat16 g_Wi1b[256 * KP];            // bf16 padded Wi1
__device__ __nv_bfloat16 g_featin[(size_t)NQ * KP];   // bf16 feat_in (103 MB)
__device__ float g_hidden[NQ * 256];
__device__ float g_skip [NQ * 3];

// ---------------- conv1: 3->64, 3x3, pad1, ReLU (naive, tiny) ----------------
__global__ void conv_enc_kernel(const float* __restrict__ inp,
                                const float* __restrict__ w,
                                const float* __restrict__ b) {
    int idx = blockIdx.x * 256 + threadIdx.x;
    if (idx >= 64 * NPIX) return;
    int oc  = idx >> 12;
    int pix = idx & 4095;
    int y = pix >> 6, x = pix & 63;
    float acc = b[oc];
    #pragma unroll
    for (int ic = 0; ic < 3; ic++) {
        #pragma unroll
        for (int dy = 0; dy < 3; dy++) {
            int yy = y + dy - 1;
            if (yy < 0 || yy > 63) continue;
            #pragma unroll
            for (int dx = 0; dx < 3; dx++) {
                int xx = x + dx - 1;
                if (xx < 0 || xx > 63) continue;
                acc += inp[ic * NPIX + yy * 64 + xx] * w[(oc * 3 + ic) * 9 + dy * 3 + dx];
            }
        }
    }
    g_enc[idx] = fmaxf(acc, 0.f);
}

// ---------------- tiled 3x3 conv body: 128 thr, tile 32x16, 16 oc, 4 px/thr --
template<int CIN, bool NHWC>
__device__ __forceinline__ void conv3x3_body(const float* __restrict__ in,
                                             const float* __restrict__ w,
                                             const float* __restrict__ bias,
                                             float* __restrict__ out) {
    __shared__ float sIn[4][18][36];
    __shared__ float sW[576];       // 16 oc x 4 ic x 9
    const int tid = threadIdx.x;
    const int tile = blockIdx.x;               // 8 tiles: 2 x-tiles * 4 y-tiles
    const int x0 = (tile & 1) * 32;
    const int y0 = (tile >> 1) * 16;
    const int oc0 = blockIdx.y * 16;
    const int tx = (tid & 7) * 4;
    const int ty = tid >> 3;

    float acc[16][4];
    #pragma unroll
    for (int i = 0; i < 16; i++)
        #pragma unroll
        for (int p = 0; p < 4; p++) acc[i][p] = 0.f;

    for (int icb = 0; icb < CIN; icb += 4) {
        // weights: 16 oc * 36 consecutive floats each
        for (int idx = tid; idx < 576; idx += 128) {
            int oc = idx / 36, r = idx % 36;
            sW[idx] = w[((size_t)(oc0 + oc) * CIN + icb) * 9 + r];
        }
        // input patch 4 x 18 x 34
        for (int idx = tid; idx < 4 * 18 * 34; idx += 128) {
            int ic = idx / (18 * 34);
            int rem = idx % (18 * 34);
            int row = rem / 34, col = rem % 34;
            int gy = y0 + row - 1, gx = x0 + col - 1;
            float v = 0.f;
            if (gy >= 0 && gy < 64 && gx >= 0 && gx < 64)
                v = in[(icb + ic) * NPIX + gy * 64 + gx];
            sIn[ic][row][col] = v;
        }
        __syncthreads();
        #pragma unroll
        for (int ic = 0; ic < 4; ic++) {
            float r_[3][6];
            #pragma unroll
            for (int ry = 0; ry < 3; ry++)
                #pragma unroll
                for (int cx = 0; cx < 6; cx++)
                    r_[ry][cx] = sIn[ic][ty + ry][tx + cx];
            #pragma unroll
            for (int oc = 0; oc < 16; oc++) {
                #pragma unroll
                for (int qf = 0; qf < 9; qf++) {
                    float wv = sW[oc * 36 + ic * 9 + qf];
                    int dy = qf / 3, dx = qf % 3;
                    #pragma unroll
                    for (int p = 0; p < 4; p++)
                        acc[oc][p] += wv * r_[dy][p + dx];
                }
            }
        }
        __syncthreads();
    }
    #pragma unroll
    for (int oc = 0; oc < 16; oc++) {
        float bb = bias[oc0 + oc];
        #pragma unroll
        for (int p = 0; p < 4; p++) {
            float v = acc[oc][p] + bb;
            int y = y0 + ty, x = x0 + tx + p;
            if (NHWC) out[(y * 64 + x) * 256 + oc0 + oc] = v;
            else      out[(oc0 + oc) * NPIX + y * 64 + x] = v;
        }
    }
}

__global__ void conv_ch_kernel(const float* __restrict__ w, const float* __restrict__ b) {
    conv3x3_body<64, false>(g_enc, w, b, g_feat);
}

__global__ void conv_qkv_kernel(const float* __restrict__ wq, const float* __restrict__ bq,
                                const float* __restrict__ wk, const float* __restrict__ bk,
                                const float* __restrict__ wv, const float* __restrict__ bv) {
    const float* w; const float* b; float* out;
    if (blockIdx.z == 0)      { w = wq; b = bq; out = g_fq; }
    else if (blockIdx.z == 1) { w = wk; b = bk; out = g_fk; }
    else                      { w = wv; b = bv; out = g_fv; }
    conv3x3_body<256, true>(g_feat, w, b, out);
}

// ---------------- grouped 5x5 conv (8 groups of 32->32), pad2 --------------
// grid (16 tiles, 8 groups, 2 oc-halves), 256 thr, 16 oc each
__global__ void conv_off1_kernel(const float* __restrict__ w, const float* __restrict__ bias) {
    const int g = blockIdx.y;
    const int oc0 = blockIdx.z * 16;
    const int tile = blockIdx.x;            // 16 tiles of 16x16
    const int x0 = (tile & 3) * 16, y0 = (tile >> 2) * 16;
    const int tid = threadIdx.x;
    const int lx = tid & 15, ly = tid >> 4;
    const int x = x0 + lx, y = y0 + ly;
    __shared__ float sIn[20][20];
    __shared__ float sW[400];
    float acc[16];
    #pragma unroll
    for (int i = 0; i < 16; i++) acc[i] = 0.f;

    for (int ic = 0; ic < 32; ic++) {
        for (int idx = tid; idx < 400; idx += 256) {
            int row = idx / 20, col = idx % 20;
            int gy = y0 + row - 2, gx = x0 + col - 2;
            float v = 0.f;
            if (gy >= 0 && gy < 64 && gx >= 0 && gx < 64)
                v = g_feat[(g * 32 + ic) * NPIX + gy * 64 + gx];
            sIn[row][col] = v;
        }
        for (int idx = tid; idx < 400; idx += 256) {
            int oc = idx / 25, p = idx % 25;
            sW[idx] = w[((g * 32 + oc0 + oc) * 32 + ic) * 25 + p];
        }
        __syncthreads();
        float r[25];
        #pragma unroll
        for (int p = 0; p < 25; p++) r[p] = sIn[ly + p / 5][lx + p % 5];
        #pragma unroll
        for (int oc = 0; oc < 16; oc++) {
            float a = acc[oc];
            #pragma unroll
            for (int p = 0; p < 25; p++) a += sW[oc * 25 + p] * r[p];
            acc[oc] = a;
        }
        __syncthreads();
    }
    #pragma unroll
    for (int oc = 0; oc < 16; oc++)
        g_o[(y * 64 + x) * 256 + g * 32 + oc0 + oc] = acc[oc] + bias[g * 32 + oc0 + oc];
}

// ---------------- LayerNorm(256 ch) + exact GELU ---------------------------
__global__ void ln_gelu_kernel(const float* __restrict__ lng, const float* __restrict__ lnb) {
    const int pix = blockIdx.x;
    const int c = threadIdx.x;
    float x = g_o[pix * 256 + c];
    __shared__ float red[256];
    __shared__ float s_mu, s_var;
    red[c] = x; __syncthreads();
    for (int s = 128; s > 0; s >>= 1) { if (c < s) red[c] += red[c + s]; __syncthreads(); }
    if (c == 0) s_mu = red[0] / 256.f;
    __syncthreads();
    float d = x - s_mu;
    red[c] = d * d; __syncthreads();
    for (int s = 128; s > 0; s >>= 1) { if (c < s) red[c] += red[c + s]; __syncthreads(); }
    if (c == 0) s_var = red[0] / 256.f;
    __syncthreads();
    float xn = d / sqrtf(s_var + 1e-5f) * lng[c] + lnb[c];
    float ge = 0.5f * xn * (1.0f + erff(xn * 0.7071067811865475f));
    g_actv[pix * 256 + c] = ge;
}

// ---------------- 1x1 conv 256->98, no bias --------------------------------
__global__ void conv_off2_kernel(const float* __restrict__ w) {
    const int pix = blockIdx.x;
    const int tid = threadIdx.x; // 128
    __shared__ float sx[256];
    sx[tid] = g_actv[pix * 256 + tid];
    sx[tid + 128] = g_actv[pix * 256 + tid + 128];
    __syncthreads();
    if (tid < 98) {
        float a = 0.f;
        #pragma unroll 8
        for (int c = 0; c < 256; c++) a += w[tid * 256 + c] * sx[c];
        g_offs[pix * 98 + tid] = a;
    }
}

// ---------------- weight prep ----------------------------------------------
__global__ void transpose_wc1_kernel(const float* __restrict__ Wc1) {
    int idx = blockIdx.x * 256 + threadIdx.x;
    if (idx >= 98 * 256) return;
    int j = idx / 256, c = idx % 256;
    g_Wc1T[idx] = Wc1[c * 98 + j];
}
__global__ void pad_wi1_kernel(const float* __restrict__ Wi1) {
    int idx = blockIdx.x * 256 + threadIdx.x;
    if (idx >= 256 * KP) return;
    int n = idx / KP, k = idx % KP;
    g_Wi1b[idx] = __float2bfloat16((k < 12546) ? Wi1[n * 12546 + k] : 0.f);
}

// ---------------- per-query deformable attention ---------------------------
__global__ void query_kernel(const float* __restrict__ coord,
                             const float* __restrict__ cell,
                             const float* __restrict__ inp,
                             const float* __restrict__ bc1,
                             const float* __restrict__ Wc2,
                             const float* __restrict__ bc2) {
    const int q = blockIdx.x;
    const int tid = threadIdx.x;     // 256
    const int lane = tid & 31;
    const int head = tid >> 5;

    __shared__ int   s_pix[49];
    __shared__ float s_mask[49];
    __shared__ float s_rel[98];
    __shared__ float s_logit[49 * 8];
    __shared__ float s_hid[256];
    __shared__ float s_wc[49];

    const float cy = coord[2 * q], cx = coord[2 * q + 1];
    const float gqx = ((cx + 1.f) * 64.f - 1.f) * 0.5f;
    const float gqy = ((cy + 1.f) * 64.f - 1.f) * 0.5f;
    // nearest base (coord_lr + offsets sampling)
    const float rx = rintf(gqx), ry = rintf(gqy);
    const bool m0 = (rx >= 0.f) && (rx < 64.f) && (ry >= 0.f) && (ry < 64.f);
    const float m0f = m0 ? 1.f : 0.f;
    const int ixq = min(max((int)rx, 0), 63);
    const int iyq = min(max((int)ry, 0), 63);
    const float sck_y = m0f * (-1.f + 1.f / 64.f + (2.f / 64.f) * (float)iyq);
    const float sck_x = m0f * (-1.f + 1.f / 64.f + (2.f / 64.f) * (float)ixq);

    if (tid < 49) {
        int k = tid;
        float o0 = g_offs[(iyq * 64 + ixq) * 98 + 2 * k]     * m0f;
        float o1 = g_offs[(iyq * 64 + ixq) * 98 + 2 * k + 1] * m0f;
        float offy = tanhf(o0) * (2.f / 63.f);
        float offx = tanhf(o1) * (2.f / 63.f);
        float dy = (float)(k / 7 - 3) * (2.f / 64.f);
        float dx = (float)(k % 7 - 3) * (2.f / 64.f);
        float py = sck_y + dy + offy;
        float px = sck_x + dx + offx;
        float gxk = ((px + 1.f) * 64.f - 1.f) * 0.5f;
        float gyk = ((py + 1.f) * 64.f - 1.f) * 0.5f;
        float rxk = rintf(gxk), ryk = rintf(gyk);
        bool mk = (rxk >= 0.f) && (rxk < 64.f) && (ryk >= 0.f) && (ryk < 64.f);
        s_pix[k]  = min(max((int)ryk, 0), 63) * 64 + min(max((int)rxk, 0), 63);
        s_mask[k] = mk ? 1.f : 0.f;
        s_rel[2 * k]     = (cy - py) * 64.f;
        s_rel[2 * k + 1] = (cx - px) * 64.f;
    }
    __syncthreads();

    // q: bilinear zeros-padding sample of fq (per channel = tid)
    float x0f = floorf(gqx), y0f = floorf(gqy);
    float wx = gqx - x0f, wy = gqy - y0f;
    int x0 = (int)x0f, y0 = (int)y0f;
    float qv = 0.f;
    #pragma unroll
    for (int dyc = 0; dyc < 2; dyc++) {
        #pragma unroll
        for (int dxc = 0; dxc < 2; dxc++) {
            int xi = x0 + dxc, yi = y0 + dyc;
            float wgt = (dxc ? wx : 1.f - wx) * (dyc ? wy : 1.f - wy);
            if (xi >= 0 && xi < 64 && yi >= 0 && yi < 64)
                qv += wgt * g_fq[(yi * 64 + xi) * 256 + tid];
        }
    }

    // attention logits: per sample, per head dot over 32 dims (warp==head)
    for (int k = 0; k < 49; k++) {
        float kv = s_mask[k] * g_fk[s_pix[k] * 256 + tid];
        float p = qv * kv;
        p += __shfl_xor_sync(0xffffffffu, p, 16);
        p += __shfl_xor_sync(0xffffffffu, p, 8);
        p += __shfl_xor_sync(0xffffffffu, p, 4);
        p += __shfl_xor_sync(0xffffffffu, p, 2);
        p += __shfl_xor_sync(0xffffffffu, p, 1);
        if (lane == 0) s_logit[k * 8 + head] = p * 0.17677669529663687f;
    }
    __syncthreads();

    // wcoord MLP: 98 -> 256 (relu) -> 49
    {
        float h = bc1[tid];
        #pragma unroll 7
        for (int j = 0; j < 98; j++) h += g_Wc1T[j * 256 + tid] * s_rel[j];
        s_hid[tid] = fmaxf(h, 0.f);
    }
    __syncthreads();
    if (tid < 49) {
        float a = bc2[tid];
        #pragma unroll 8
        for (int c = 0; c < 256; c++) a += Wc2[tid * 256 + c] * s_hid[c];
        s_wc[tid] = a;
    }
    __syncthreads();

    // softmax over k per head
    if (tid < 8) {
        int hh = tid;
        float mx = -1e30f;
        for (int k = 0; k < 49; k++) {
            float t = s_wc[k] + s_logit[k * 8 + hh];
            if (t > mx) mx = t;
        }
        float sum = 0.f;
        for (int k = 0; k < 49; k++) {
            float e = expf(s_wc[k] + s_logit[k * 8 + hh] - mx);
            s_logit[k * 8 + hh] = e;
            sum += e;
        }
        float inv = 1.f / sum;
        for (int k = 0; k < 49; k++) s_logit[k * 8 + hh] *= inv;
    }
    __syncthreads();

    // feat_in = v * attn   (NHWC gather of fv, coalesced) -> bf16
    size_t base = (size_t)q * KP;
    for (int k = 0; k < 49; k++) {
        float v = s_mask[k] * g_fv[s_pix[k] * 256 + tid];
        g_featin[base + k * 256 + tid] = __float2bfloat16(v * s_logit[k * 8 + head]);
    }
    if (tid < 32) {
        float val = 0.f;
        if (tid == 0) val = cell[2 * q] * 64.f;
        else if (tid == 1) val = cell[2 * q + 1] * 64.f;
        g_featin[base + 12544 + tid] = __float2bfloat16(val);
    }

    // skip: bilinear border sample of inp
    if (tid < 3) {
        float gxc = fminf(fmaxf(gqx, 0.f), 63.f);
        float gyc = fminf(fmaxf(gqy, 0.f), 63.f);
        float xf = floorf(gxc), yf = floorf(gyc);
        float bx = gxc - xf, by = gyc - yf;
        int xa = (int)xf, ya = (int)yf;
        int xb = min(xa + 1, 63), yb = min(ya + 1, 63);
        const float* ch = inp + tid * NPIX;
        float s = (1.f - bx) * (1.f - by) * ch[ya * 64 + xa]
                +        bx  * (1.f - by) * ch[ya * 64 + xb]
                + (1.f - bx) *        by  * ch[yb * 64 + xa]
                +        bx  *        by  * ch[yb * 64 + xb];
        g_skip[q * 3 + tid] = s;
    }
}

// ---------------- GEMM: hidden = relu(feat_in @ Wi1^T + b), bf16 HMMA ------
// M=4096, N=256, K=12576; BM=128, BN=64, BK=32, 256 thr (8 warps, 4m x 2n),
// warp tile 32x32 via mma.sync.m16n8k16 (2 m-frags x 4 n-frags)
__global__ void gemm_mma_kernel(const float* __restrict__ bi1) {
    __shared__ __align__(16) __nv_bfloat16 sA[128 * 40];  // stride 40 (pad 8)
    __shared__ __align__(16) __nv_bfloat16 sB[64 * 40];
    const int tid  = threadIdx.x;
    const int warp = tid >> 5, lane = tid & 31;
    const int wm = warp & 3, wn = warp >> 2;
    const int bm = blockIdx.x * 128, bn = blockIdx.y * 64;

    float acc[2][4][4];
    #pragma unroll
    for (int i = 0; i < 2; i++)
        #pragma unroll
        for (int j = 0; j < 4; j++)
            #pragma unroll
            for (int r = 0; r < 4; r++) acc[i][j][r] = 0.f;

    // global load mapping
    const int arow = tid >> 1, akh = (tid & 1) * 16;   // A: 128 rows x 32 cols
    const int brow = tid >> 2, bkh = (tid & 3) * 8;    // B: 64 rows x 32 cols
    const __nv_bfloat16* gA = g_featin + (size_t)(bm + arow) * KP + akh;
    const __nv_bfloat16* gB = g_Wi1b   + (size_t)(bn + brow) * KP + bkh;

    // ldmatrix smem addresses
    // A x4: lanes {0-7: r, 8-15: r+8, 16-23: r (c+8), 24-31: r+8 (c+8)}
    const int a_r = ((lane >> 3) & 1) * 8 + (lane & 7);
    const int a_c = (lane >> 4) * 8;
    // B x4: lanes {0-7: rows nb, 8-15: rows nb (c+8), 16-23: rows nb+8, 24-31: rows nb+8 (c+8)}
    const int b_r = ((lane >> 4) & 1) * 8 + (lane & 7);
    const int b_c = ((lane >> 3) & 1) * 8;

    uint4 pa0 = *(const uint4*)(gA);
    uint4 pa1 = *(const uint4*)(gA + 8);
    uint4 pb  = *(const uint4*)(gB);

    const int NIT = KP / 32;  // 393
    for (int it = 0; it < NIT; it++) {
        *(uint4*)&sA[arow * 40 + akh]     = pa0;
        *(uint4*)&sA[arow * 40 + akh + 8] = pa1;
        *(uint4*)&sB[brow * 40 + bkh]     = pb;
        __syncthreads();
        if (it + 1 < NIT) {
            const __nv_bfloat16* nA = gA + (it + 1) * 32;
            pa0 = *(const uint4*)(nA);
            pa1 = *(const uint4*)(nA + 8);
            pb  = *(const uint4*)(gB + (it + 1) * 32);
        }
        #pragma unroll
        for (int k16 = 0; k16 < 2; k16++) {
            uint32_t af[2][4];
            #pragma unroll
            for (int am = 0; am < 2; am++) {
                uint32_t addr = (uint32_t)__cvta_generic_to_shared(
                    &sA[(wm * 32 + am * 16 + a_r) * 40 + k16 * 16 + a_c]);
                asm volatile("ldmatrix.sync.aligned.m8n8.x4.shared.b16 {%0,%1,%2,%3}, [%4];"
                             : "=r"(af[am][0]), "=r"(af[am][1]), "=r"(af[am][2]), "=r"(af[am][3])
                             : "r"(addr));
            }
            uint32_t bfr[2][4];
            #pragma unroll
            for (int bp = 0; bp < 2; bp++) {
                uint32_t addr = (uint32_t)__cvta_generic_to_shared(
                    &sB[(wn * 32 + bp * 16 + b_r) * 40 + k16 * 16 + b_c]);
                asm volatile("ldmatrix.sync.aligned.m8n8.x4.shared.b16 {%0,%1,%2,%3}, [%4];"
                             : "=r"(bfr[bp][0]), "=r"(bfr[bp][1]), "=r"(bfr[bp][2]), "=r"(bfr[bp][3])
                             : "r"(addr));
            }
            #pragma unroll
            for (int am = 0; am < 2; am++) {
                #pragma unroll
                for (int bt = 0; bt < 4; bt++) {
                    uint32_t b0 = bfr[bt >> 1][2 * (bt & 1)];
                    uint32_t b1 = bfr[bt >> 1][2 * (bt & 1) + 1];
                    asm volatile(
                        "mma.sync.aligned.m16n8k16.row.col.f32.bf16.bf16.f32 "
                        "{%0,%1,%2,%3}, {%4,%5,%6,%7}, {%8,%9}, {%0,%1,%2,%3};"
                        : "+f"(acc[am][bt][0]), "+f"(acc[am][bt][1]),
                          "+f"(acc[am][bt][2]), "+f"(acc[am][bt][3])
                        : "r"(af[am][0]), "r"(af[am][1]), "r"(af[am][2]), "r"(af[am][3]),
                          "r"(b0), "r"(b1));
                }
            }
        }
        __syncthreads();
    }

    // epilogue: relu(acc + bias) -> g_hidden
    const int dr = lane >> 2, dn = (lane & 3) * 2;
    #pragma unroll
    for (int am = 0; am < 2; am++) {
        int mrow = bm + wm * 32 + am * 16;
        #pragma unroll
        for (int bt = 0; bt < 4; bt++) {
            int ncol = bn + wn * 32 + bt * 8 + dn;
            float bb0 = bi1[ncol], bb1 = bi1[ncol + 1];
            g_hidden[(mrow + dr) * 256 + ncol]         = fmaxf(acc[am][bt][0] + bb0, 0.f);
            g_hidden[(mrow + dr) * 256 + ncol + 1]     = fmaxf(acc[am][bt][1] + bb1, 0.f);
            g_hidden[(mrow + dr + 8) * 256 + ncol]     = fmaxf(acc[am][bt][2] + bb0, 0.f);
            g_hidden[(mrow + dr + 8) * 256 + ncol + 1] = fmaxf(acc[am][bt][3] + bb1, 0.f);
        }
    }
}

// ---------------- final: pred = Wi2 @ hidden + bi2 + skip ------------------
__global__ void final_kernel(const float* __restrict__ Wi2,
                             const float* __restrict__ bi2,
                             float* __restrict__ out) {
    int idx = blockIdx.x * 128 + threadIdx.x;
    if (idx >= NQ * 3) return;
    int q = idx / 3, o = idx % 3;
    float acc = bi2[o];
    const float* h = g_hidden + q * 256;
    const float* w = Wi2 + o * 256;
    #pragma unroll 8
    for (int c = 0; c < 256; c++) acc += w[c] * h[c];
    out[idx] = acc + g_skip[idx];
}

// ---------------- launcher -------------------------------------------------
extern "C" void kernel_launch(void* const* d_in, const int* in_sizes, int n_in,
                              void* d_out, int out_size) {
    const float* inp    = (const float*)d_in[0];
    const float* coord  = (const float*)d_in[1];
    const float* cell   = (const float*)d_in[2];
    const float* W_enc  = (const float*)d_in[3];
    const float* b_enc  = (const float*)d_in[4];
    const float* W_ch   = (const float*)d_in[5];
    const float* b_ch   = (const float*)d_in[6];
    const float* W_q    = (const float*)d_in[7];
    const float* b_q    = (const float*)d_in[8];
    const float* W_k    = (const float*)d_in[9];
    const float* b_k    = (const float*)d_in[10];
    const float* W_v    = (const float*)d_in[11];
    const float* b_v    = (const float*)d_in[12];
    const float* W_off1 = (const float*)d_in[13];
    const float* b_off1 = (const float*)d_in[14];
    const float* ln_g   = (const float*)d_in[15];
    const float* ln_b   = (const float*)d_in[16];
    const float* W_off2 = (const float*)d_in[17];
    const float* Wc1    = (const float*)d_in[18];
    const float* bc1    = (const float*)d_in[19];
    const float* Wc2    = (const float*)d_in[20];
    const float* bc2    = (const float*)d_in[21];
    const float* Wi1    = (const float*)d_in[22];
    const float* bi1    = (const float*)d_in[23];
    const float* Wi2    = (const float*)d_in[24];
    const float* bi2    = (const float*)d_in[25];
    float* out = (float*)d_out;

    conv_enc_kernel<<<(64 * NPIX + 255) / 256, 256>>>(inp, W_enc, b_enc);
    conv_ch_kernel<<<dim3(8, 16), 128>>>(W_ch, b_ch);
    conv_qkv_kernel<<<dim3(8, 16, 3), 128>>>(W_q, b_q, W_k, b_k, W_v, b_v);
    conv_off1_kernel<<<dim3(16, 8, 2), 256>>>(W_off1, b_off1);
    ln_gelu_kernel<<<NPIX, 256>>>(ln_g, ln_b);
    conv_off2_kernel<<<NPIX, 128>>>(W_off2);
    transpose_wc1_kernel<<<(98 * 256 + 255) / 256, 256>>>(Wc1);
    pad_wi1_kernel<<<(256 * KP + 255) / 256, 256>>>(Wi1);
    query_kernel<<<NQ, 256>>>(coord, cell, inp, bc1, Wc2, bc2);
    gemm_mma_kernel<<<dim3(32, 4), 256>>>(bi1);
    final_kernel<<<(NQ * 3 + 127) / 128, 128>>>(Wi2, bi2, out);
}

// round 13
// speedup vs baseline: 1.9590x; 1.3614x over previous
#include <cuda_runtime.h>
#include <cuda_bf16.h>
#include <stdint.h>
#include <math.h>

// ---------------- problem constants ----------------
#define NPIX 4096
#define NQ   4096
#define KP   12576   // 12546 padded up to 32*393

// ---------------- scratch (device globals; no allocations) ----------------
__device__ float g_enc [64  * NPIX];          // NCHW  64x64x64
__device__ float g_feat[256 * NPIX];          // NCHW 256x64x64 (for off1 path)
__device__ __nv_bfloat16 g_featb[NPIX * 256]; // NHWC bf16 (for qkv implicit gemm)
__device__ float g_fq  [NPIX * 256];          // NHWC
__device__ float g_fk  [NPIX * 256];          // NHWC
__device__ float g_fv  [NPIX * 256];          // NHWC
__device__ float g_o   [NPIX * 256];          // NHWC (grouped conv out)
__device__ float g_actv[NPIX * 256];          // NHWC (LN+GELU out)
__device__ float g_offs[NPIX * 98];           // NHWC
__device__ float g_Wc1T[98 * 256];            // transposed Wc1
__device__ __nv_bfloat16 g_Wqkvb[3 * 9 * 256 * 256];  // per-tap [oc,ic] bf16
__device__ __nv_bfloat16 g_Wi1b[256 * KP];            // bf16 padded Wi1
__device__ __nv_bfloat16 g_featin[(size_t)NQ * KP];   // bf16 feat_in (103 MB)
__device__ float g_hidden[NQ * 256];
__device__ float g_skip [NQ * 3];

// ---------------- conv1: 3->64, 3x3, pad1, ReLU (naive, tiny) ----------------
__global__ void conv_enc_kernel(const float* __restrict__ inp,
                                const float* __restrict__ w,
                                const float* __restrict__ b) {
    int idx = blockIdx.x * 256 + threadIdx.x;
    if (idx >= 64 * NPIX) return;
    int oc  = idx >> 12;
    int pix = idx & 4095;
    int y = pix >> 6, x = pix & 63;
    float acc = b[oc];
    #pragma unroll
    for (int ic = 0; ic < 3; ic++) {
        #pragma unroll
        for (int dy = 0; dy < 3; dy++) {
            int yy = y + dy - 1;
            if (yy < 0 || yy > 63) continue;
            #pragma unroll
            for (int dx = 0; dx < 3; dx++) {
                int xx = x + dx - 1;
                if (xx < 0 || xx > 63) continue;
                acc += inp[ic * NPIX + yy * 64 + xx] * w[(oc * 3 + ic) * 9 + dy * 3 + dx];
            }
        }
    }
    g_enc[idx] = fmaxf(acc, 0.f);
}

// ---------------- conv_ch: 64->256, 3x3, fp32 tiled; emits NCHW f32 + NHWC bf16
__global__ void conv_ch_kernel(const float* __restrict__ w, const float* __restrict__ b) {
    __shared__ float sIn[4][18][36];
    __shared__ float sW[576];
    const int tid = threadIdx.x;
    const int tile = blockIdx.x;
    const int x0 = (tile & 1) * 32;
    const int y0 = (tile >> 1) * 16;
    const int oc0 = blockIdx.y * 16;
    const int tx = (tid & 7) * 4;
    const int ty = tid >> 3;

    float acc[16][4];
    #pragma unroll
    for (int i = 0; i < 16; i++)
        #pragma unroll
        for (int p = 0; p < 4; p++) acc[i][p] = 0.f;

    for (int icb = 0; icb < 64; icb += 4) {
        for (int idx = tid; idx < 576; idx += 128) {
            int oc = idx / 36, r = idx % 36;
            sW[idx] = w[((size_t)(oc0 + oc) * 64 + icb) * 9 + r];
        }
        for (int idx = tid; idx < 4 * 18 * 34; idx += 128) {
            int ic = idx / (18 * 34);
            int rem = idx % (18 * 34);
            int row = rem / 34, col = rem % 34;
            int gy = y0 + row - 1, gx = x0 + col - 1;
            float v = 0.f;
            if (gy >= 0 && gy < 64 && gx >= 0 && gx < 64)
                v = g_enc[(icb + ic) * NPIX + gy * 64 + gx];
            sIn[ic][row][col] = v;
        }
        __syncthreads();
        #pragma unroll
        for (int ic = 0; ic < 4; ic++) {
            float r_[3][6];
            #pragma unroll
            for (int ry = 0; ry < 3; ry++)
                #pragma unroll
                for (int cx = 0; cx < 6; cx++)
                    r_[ry][cx] = sIn[ic][ty + ry][tx + cx];
            #pragma unroll
            for (int oc = 0; oc < 16; oc++) {
                #pragma unroll
                for (int qf = 0; qf < 9; qf++) {
                    float wv = sW[oc * 36 + ic * 9 + qf];
                    int dy = qf / 3, dx = qf % 3;
                    #pragma unroll
                    for (int p = 0; p < 4; p++)
                        acc[oc][p] += wv * r_[dy][p + dx];
                }
            }
        }
        __syncthreads();
    }
    #pragma unroll
    for (int oc = 0; oc < 16; oc++) {
        float bb = b[oc0 + oc];
        #pragma unroll
        for (int p = 0; p < 4; p++) {
            float v = acc[oc][p] + bb;
            int y = y0 + ty, x = x0 + tx + p;
            g_feat[(oc0 + oc) * NPIX + y * 64 + x] = v;
            g_featb[(y * 64 + x) * 256 + oc0 + oc] = __float2bfloat16(v);
        }
    }
}

// ---------------- qkv weight prep: per-tap [oc, ic] bf16 -------------------
__global__ void prep_wqkv_kernel(const float* __restrict__ wq,
                                 const float* __restrict__ wk,
                                 const float* __restrict__ wv) {
    int idx = blockIdx.x * 256 + threadIdx.x;
    if (idx >= 3 * 9 * 65536) return;
    int z   = idx / (9 * 65536);
    int rem = idx % (9 * 65536);
    int tap = rem / 65536;
    int r2  = rem % 65536;
    int oc = r2 >> 8, ic = r2 & 255;
    const float* w = (z == 0) ? wq : (z == 1) ? wk : wv;
    g_Wqkvb[idx] = __float2bfloat16(w[(oc * 256 + ic) * 9 + tap]);
}

// ---------------- qkv convs as bf16 implicit GEMM HMMA ---------------------
// M=4096 px, N=256 oc, K = 9 taps x 256 ic; BM=128 (2 image rows), BN=64, BK=32
__global__ void conv_qkv_mma_kernel(const float* __restrict__ bq,
                                    const float* __restrict__ bk,
                                    const float* __restrict__ bv) {
    __shared__ __align__(16) __nv_bfloat16 sA[128 * 40];
    __shared__ __align__(16) __nv_bfloat16 sB[64 * 40];
    const int tid  = threadIdx.x;
    const int warp = tid >> 5, lane = tid & 31;
    const int wm = warp & 3, wn = warp >> 2;
    const int bm = blockIdx.x * 128, bn = blockIdx.y * 64;
    const int z = blockIdx.z;
    const float* bias = (z == 0) ? bq : (z == 1) ? bk : bv;
    float* out = (z == 0) ? g_fq : (z == 1) ? g_fk : g_fv;
    const __nv_bfloat16* wbase = g_Wqkvb + (size_t)z * 9 * 65536;

    float acc[2][4][4];
    #pragma unroll
    for (int i = 0; i < 2; i++)
        #pragma unroll
        for (int j = 0; j < 4; j++)
            #pragma unroll
            for (int r = 0; r < 4; r++) acc[i][j][r] = 0.f;

    const int arow = tid >> 1, akh = (tid & 1) * 16;
    const int brow = tid >> 2, bkh = (tid & 3) * 8;
    const int p   = bm + arow;
    const int pxx = p & 63, pyy = p >> 6;

    const int a_r = ((lane >> 3) & 1) * 8 + (lane & 7);
    const int a_c = (lane >> 4) * 8;
    const int b_r = ((lane >> 4) & 1) * 8 + (lane & 7);
    const int b_c = ((lane >> 3) & 1) * 8;

    const uint4 zero4 = make_uint4(0, 0, 0, 0);
    uint4 pa0, pa1, pb;
    // iteration it = tap*8 + kb
    auto load_it = [&](int it, uint4& a0, uint4& a1, uint4& b) {
        int tap = it >> 3, kb = it & 7;
        int dy = tap / 3 - 1, dx = tap % 3 - 1;
        bool valid = (pxx + dx >= 0) && (pxx + dx < 64) && (pyy + dy >= 0) && (pyy + dy < 64);
        if (valid) {
            const __nv_bfloat16* gA = g_featb + (size_t)(p + dy * 64 + dx) * 256 + kb * 32 + akh;
            a0 = *(const uint4*)gA;
            a1 = *(const uint4*)(gA + 8);
        } else { a0 = zero4; a1 = zero4; }
        b = *(const uint4*)(wbase + (size_t)tap * 65536 + (size_t)(bn + brow) * 256 + kb * 32 + bkh);
    };

    load_it(0, pa0, pa1, pb);
    const int NIT = 72;
    for (int it = 0; it < NIT; it++) {
        *(uint4*)&sA[arow * 40 + akh]     = pa0;
        *(uint4*)&sA[arow * 40 + akh + 8] = pa1;
        *(uint4*)&sB[brow * 40 + bkh]     = pb;
        __syncthreads();
        if (it + 1 < NIT) load_it(it + 1, pa0, pa1, pb);
        #pragma unroll
        for (int k16 = 0; k16 < 2; k16++) {
            uint32_t af[2][4];
            #pragma unroll
            for (int am = 0; am < 2; am++) {
                uint32_t addr = (uint32_t)__cvta_generic_to_shared(
                    &sA[(wm * 32 + am * 16 + a_r) * 40 + k16 * 16 + a_c]);
                asm volatile("ldmatrix.sync.aligned.m8n8.x4.shared.b16 {%0,%1,%2,%3}, [%4];"
                             : "=r"(af[am][0]), "=r"(af[am][1]), "=r"(af[am][2]), "=r"(af[am][3])
                             : "r"(addr));
            }
            uint32_t bfr[2][4];
            #pragma unroll
            for (int bp = 0; bp < 2; bp++) {
                uint32_t addr = (uint32_t)__cvta_generic_to_shared(
                    &sB[(wn * 32 + bp * 16 + b_r) * 40 + k16 * 16 + b_c]);
                asm volatile("ldmatrix.sync.aligned.m8n8.x4.shared.b16 {%0,%1,%2,%3}, [%4];"
                             : "=r"(bfr[bp][0]), "=r"(bfr[bp][1]), "=r"(bfr[bp][2]), "=r"(bfr[bp][3])
                             : "r"(addr));
            }
            #pragma unroll
            for (int am = 0; am < 2; am++) {
                #pragma unroll
                for (int bt = 0; bt < 4; bt++) {
                    uint32_t b0 = bfr[bt >> 1][2 * (bt & 1)];
                    uint32_t b1 = bfr[bt >> 1][2 * (bt & 1) + 1];
                    asm volatile(
                        "mma.sync.aligned.m16n8k16.row.col.f32.bf16.bf16.f32 "
                        "{%0,%1,%2,%3}, {%4,%5,%6,%7}, {%8,%9}, {%0,%1,%2,%3};"
                        : "+f"(acc[am][bt][0]), "+f"(acc[am][bt][1]),
                          "+f"(acc[am][bt][2]), "+f"(acc[am][bt][3])
                        : "r"(af[am][0]), "r"(af[am][1]), "r"(af[am][2]), "r"(af[am][3]),
                          "r"(b0), "r"(b1));
                }
            }
        }
        __syncthreads();
    }

    const int dr = lane >> 2, dn = (lane & 3) * 2;
    #pragma unroll
    for (int am = 0; am < 2; am++) {
        int mrow = bm + wm * 32 + am * 16;
        #pragma unroll
        for (int bt = 0; bt < 4; bt++) {
            int ncol = bn + wn * 32 + bt * 8 + dn;
            float bb0 = bias[ncol], bb1 = bias[ncol + 1];
            out[(mrow + dr) * 256 + ncol]         = acc[am][bt][0] + bb0;
            out[(mrow + dr) * 256 + ncol + 1]     = acc[am][bt][1] + bb1;
            out[(mrow + dr + 8) * 256 + ncol]     = acc[am][bt][2] + bb0;
            out[(mrow + dr + 8) * 256 + ncol + 1] = acc[am][bt][3] + bb1;
        }
    }
}

// ---------------- grouped 5x5 conv (8 groups of 32->32), pad2 --------------
// grid (16 tiles, 8 groups, 4 oc-quarters), 256 thr, 8 oc each
__global__ void conv_off1_kernel(const float* __restrict__ w, const float* __restrict__ bias) {
    const int g = blockIdx.y;
    const int oc0 = blockIdx.z * 8;
    const int tile = blockIdx.x;
    const int x0 = (tile & 3) * 16, y0 = (tile >> 2) * 16;
    const int tid = threadIdx.x;
    const int lx = tid & 15, ly = tid >> 4;
    const int x = x0 + lx, y = y0 + ly;
    __shared__ float sIn[20][20];
    __shared__ float sW[200];
    float acc[8];
    #pragma unroll
    for (int i = 0; i < 8; i++) acc[i] = 0.f;

    for (int ic = 0; ic < 32; ic++) {
        for (int idx = tid; idx < 400; idx += 256) {
            int row = idx / 20, col = idx % 20;
            int gy = y0 + row - 2, gx = x0 + col - 2;
            float v = 0.f;
            if (gy >= 0 && gy < 64 && gx >= 0 && gx < 64)
                v = g_feat[(g * 32 + ic) * NPIX + gy * 64 + gx];
            sIn[row][col] = v;
        }
        if (tid < 200) {
            int oc = tid / 25, pp = tid % 25;
            sW[tid] = w[((g * 32 + oc0 + oc) * 32 + ic) * 25 + pp];
        }
        __syncthreads();
        float r[25];
        #pragma unroll
        for (int pp = 0; pp < 25; pp++) r[pp] = sIn[ly + pp / 5][lx + pp % 5];
        #pragma unroll
        for (int oc = 0; oc < 8; oc++) {
            float a = acc[oc];
            #pragma unroll
            for (int pp = 0; pp < 25; pp++) a += sW[oc * 25 + pp] * r[pp];
            acc[oc] = a;
        }
        __syncthreads();
    }
    #pragma unroll
    for (int oc = 0; oc < 8; oc++)
        g_o[(y * 64 + x) * 256 + g * 32 + oc0 + oc] = acc[oc] + bias[g * 32 + oc0 + oc];
}

// ---------------- LayerNorm(256 ch) + exact GELU (shuffle reduction) -------
__global__ void ln_gelu_kernel(const float* __restrict__ lng, const float* __restrict__ lnb) {
    const int pix = blockIdx.x;
    const int c = threadIdx.x;
    const int lane = c & 31, warp = c >> 5;
    __shared__ float sp[8];
    float x = g_o[pix * 256 + c];

    float s = x;
    #pragma unroll
    for (int o = 16; o > 0; o >>= 1) s += __shfl_xor_sync(0xffffffffu, s, o);
    if (lane == 0) sp[warp] = s;
    __syncthreads();
    float mu;
    {
        float t = (lane < 8) ? sp[lane] : 0.f;
        #pragma unroll
        for (int o = 4; o > 0; o >>= 1) t += __shfl_xor_sync(0xffffffffu, t, o);
        mu = __shfl_sync(0xffffffffu, t, 0) / 256.f;
    }
    float d = x - mu;
    float v = d * d;
    #pragma unroll
    for (int o = 16; o > 0; o >>= 1) v += __shfl_xor_sync(0xffffffffu, v, o);
    __syncthreads();
    if (lane == 0) sp[warp] = v;
    __syncthreads();
    float var;
    {
        float t = (lane < 8) ? sp[lane] : 0.f;
        #pragma unroll
        for (int o = 4; o > 0; o >>= 1) t += __shfl_xor_sync(0xffffffffu, t, o);
        var = __shfl_sync(0xffffffffu, t, 0) / 256.f;
    }
    float xn = d / sqrtf(var + 1e-5f) * lng[c] + lnb[c];
    float ge = 0.5f * xn * (1.0f + erff(xn * 0.7071067811865475f));
    g_actv[pix * 256 + c] = ge;
}

// ---------------- 1x1 conv 256->98, no bias --------------------------------
__global__ void conv_off2_kernel(const float* __restrict__ w) {
    const int pix = blockIdx.x;
    const int tid = threadIdx.x; // 128
    __shared__ float sx[256];
    sx[tid] = g_actv[pix * 256 + tid];
    sx[tid + 128] = g_actv[pix * 256 + tid + 128];
    __syncthreads();
    if (tid < 98) {
        float a = 0.f;
        #pragma unroll 8
        for (int c = 0; c < 256; c++) a += w[tid * 256 + c] * sx[c];
        g_offs[pix * 98 + tid] = a;
    }
}

// ---------------- weight prep ----------------------------------------------
__global__ void transpose_wc1_kernel(const float* __restrict__ Wc1) {
    int idx = blockIdx.x * 256 + threadIdx.x;
    if (idx >= 98 * 256) return;
    int j = idx / 256, c = idx % 256;
    g_Wc1T[idx] = Wc1[c * 98 + j];
}
__global__ void pad_wi1_kernel(const float* __restrict__ Wi1) {
    int idx = blockIdx.x * 256 + threadIdx.x;
    if (idx >= 256 * KP) return;
    int n = idx / KP, k = idx % KP;
    g_Wi1b[idx] = __float2bfloat16((k < 12546) ? Wi1[n * 12546 + k] : 0.f);
}

// ---------------- per-query deformable attention ---------------------------
__global__ void query_kernel(const float* __restrict__ coord,
                             const float* __restrict__ cell,
                             const float* __restrict__ inp,
                             const float* __restrict__ bc1,
                             const float* __restrict__ Wc2,
                             const float* __restrict__ bc2) {
    const int q = blockIdx.x;
    const int tid = threadIdx.x;     // 256
    const int lane = tid & 31;
    const int head = tid >> 5;

    __shared__ int   s_pix[49];
    __shared__ float s_mask[49];
    __shared__ float s_rel[98];
    __shared__ float s_logit[49 * 8];
    __shared__ float s_hid[256];
    __shared__ float s_wc[49];

    const float cy = coord[2 * q], cx = coord[2 * q + 1];
    const float gqx = ((cx + 1.f) * 64.f - 1.f) * 0.5f;
    const float gqy = ((cy + 1.f) * 64.f - 1.f) * 0.5f;
    const float rx = rintf(gqx), ry = rintf(gqy);
    const bool m0 = (rx >= 0.f) && (rx < 64.f) && (ry >= 0.f) && (ry < 64.f);
    const float m0f = m0 ? 1.f : 0.f;
    const int ixq = min(max((int)rx, 0), 63);
    const int iyq = min(max((int)ry, 0), 63);
    const float sck_y = m0f * (-1.f + 1.f / 64.f + (2.f / 64.f) * (float)iyq);
    const float sck_x = m0f * (-1.f + 1.f / 64.f + (2.f / 64.f) * (float)ixq);

    if (tid < 49) {
        int k = tid;
        float o0 = g_offs[(iyq * 64 + ixq) * 98 + 2 * k]     * m0f;
        float o1 = g_offs[(iyq * 64 + ixq) * 98 + 2 * k + 1] * m0f;
        float offy = tanhf(o0) * (2.f / 63.f);
        float offx = tanhf(o1) * (2.f / 63.f);
        float dy = (float)(k / 7 - 3) * (2.f / 64.f);
        float dx = (float)(k % 7 - 3) * (2.f / 64.f);
        float py = sck_y + dy + offy;
        float px = sck_x + dx + offx;
        float gxk = ((px + 1.f) * 64.f - 1.f) * 0.5f;
        float gyk = ((py + 1.f) * 64.f - 1.f) * 0.5f;
        float rxk = rintf(gxk), ryk = rintf(gyk);
        bool mk = (rxk >= 0.f) && (rxk < 64.f) && (ryk >= 0.f) && (ryk < 64.f);
        s_pix[k]  = min(max((int)ryk, 0), 63) * 64 + min(max((int)rxk, 0), 63);
        s_mask[k] = mk ? 1.f : 0.f;
        s_rel[2 * k]     = (cy - py) * 64.f;
        s_rel[2 * k + 1] = (cx - px) * 64.f;
    }
    __syncthreads();

    // q: bilinear zeros-padding sample of fq (per channel = tid)
    float x0f = floorf(gqx), y0f = floorf(gqy);
    float wx = gqx - x0f, wy = gqy - y0f;
    int x0 = (int)x0f, y0 = (int)y0f;
    float qv = 0.f;
    #pragma unroll
    for (int dyc = 0; dyc < 2; dyc++) {
        #pragma unroll
        for (int dxc = 0; dxc < 2; dxc++) {
            int xi = x0 + dxc, yi = y0 + dyc;
            float wgt = (dxc ? wx : 1.f - wx) * (dyc ? wy : 1.f - wy);
            if (xi >= 0 && xi < 64 && yi >= 0 && yi < 64)
                qv += wgt * g_fq[(yi * 64 + xi) * 256 + tid];
        }
    }

    // attention logits
    for (int k = 0; k < 49; k++) {
        float kv = s_mask[k] * g_fk[s_pix[k] * 256 + tid];
        float p = qv * kv;
        p += __shfl_xor_sync(0xffffffffu, p, 16);
        p += __shfl_xor_sync(0xffffffffu, p, 8);
        p += __shfl_xor_sync(0xffffffffu, p, 4);
        p += __shfl_xor_sync(0xffffffffu, p, 2);
        p += __shfl_xor_sync(0xffffffffu, p, 1);
        if (lane == 0) s_logit[k * 8 + head] = p * 0.17677669529663687f;
    }
    __syncthreads();

    // wcoord MLP: 98 -> 256 (relu) -> 49
    {
        float h = bc1[tid];
        #pragma unroll 7
        for (int j = 0; j < 98; j++) h += g_Wc1T[j * 256 + tid] * s_rel[j];
        s_hid[tid] = fmaxf(h, 0.f);
    }
    __syncthreads();
    if (tid < 49) {
        float a = bc2[tid];
        #pragma unroll 8
        for (int c = 0; c < 256; c++) a += Wc2[tid * 256 + c] * s_hid[c];
        s_wc[tid] = a;
    }
    __syncthreads();

    // softmax over k per head
    if (tid < 8) {
        int hh = tid;
        float mx = -1e30f;
        for (int k = 0; k < 49; k++) {
            float t = s_wc[k] + s_logit[k * 8 + hh];
            if (t > mx) mx = t;
        }
        float sum = 0.f;
        for (int k = 0; k < 49; k++) {
            float e = expf(s_wc[k] + s_logit[k * 8 + hh] - mx);
            s_logit[k * 8 + hh] = e;
            sum += e;
        }
        float inv = 1.f / sum;
        for (int k = 0; k < 49; k++) s_logit[k * 8 + hh] *= inv;
    }
    __syncthreads();

    // feat_in = v * attn -> bf16
    size_t base = (size_t)q * KP;
    for (int k = 0; k < 49; k++) {
        float v = s_mask[k] * g_fv[s_pix[k] * 256 + tid];
        g_featin[base + k * 256 + tid] = __float2bfloat16(v * s_logit[k * 8 + head]);
    }
    if (tid < 32) {
        float val = 0.f;
        if (tid == 0) val = cell[2 * q] * 64.f;
        else if (tid == 1) val = cell[2 * q + 1] * 64.f;
        g_featin[base + 12544 + tid] = __float2bfloat16(val);
    }

    // skip: bilinear border sample of inp
    if (tid < 3) {
        float gxc = fminf(fmaxf(gqx, 0.f), 63.f);
        float gyc = fminf(fmaxf(gqy, 0.f), 63.f);
        float xf = floorf(gxc), yf = floorf(gyc);
        float bx = gxc - xf, by = gyc - yf;
        int xa = (int)xf, ya = (int)yf;
        int xb = min(xa + 1, 63), yb = min(ya + 1, 63);
        const float* ch = inp + tid * NPIX;
        float s = (1.f - bx) * (1.f - by) * ch[ya * 64 + xa]
                +        bx  * (1.f - by) * ch[ya * 64 + xb]
                + (1.f - bx) *        by  * ch[yb * 64 + xa]
                +        bx  *        by  * ch[yb * 64 + xb];
        g_skip[q * 3 + tid] = s;
    }
}

// ---------------- GEMM: hidden = relu(feat_in @ Wi1^T + b), bf16 HMMA ------
__global__ void gemm_mma_kernel(const float* __restrict__ bi1) {
    __shared__ __align__(16) __nv_bfloat16 sA[128 * 40];
    __shared__ __align__(16) __nv_bfloat16 sB[64 * 40];
    const int tid  = threadIdx.x;
    const int warp = tid >> 5, lane = tid & 31;
    const int wm = warp & 3, wn = warp >> 2;
    const int bm = blockIdx.x * 128, bn = blockIdx.y * 64;

    float acc[2][4][4];
    #pragma unroll
    for (int i = 0; i < 2; i++)
        #pragma unroll
        for (int j = 0; j < 4; j++)
            #pragma unroll
            for (int r = 0; r < 4; r++) acc[i][j][r] = 0.f;

    const int arow = tid >> 1, akh = (tid & 1) * 16;
    const int brow = tid >> 2, bkh = (tid & 3) * 8;
    const __nv_bfloat16* gA = g_featin + (size_t)(bm + arow) * KP + akh;
    const __nv_bfloat16* gB = g_Wi1b   + (size_t)(bn + brow) * KP + bkh;

    const int a_r = ((lane >> 3) & 1) * 8 + (lane & 7);
    const int a_c = (lane >> 4) * 8;
    const int b_r = ((lane >> 4) & 1) * 8 + (lane & 7);
    const int b_c = ((lane >> 3) & 1) * 8;

    uint4 pa0 = *(const uint4*)(gA);
    uint4 pa1 = *(const uint4*)(gA + 8);
    uint4 pb  = *(const uint4*)(gB);

    const int NIT = KP / 32;  // 393
    for (int it = 0; it < NIT; it++) {
        *(uint4*)&sA[arow * 40 + akh]     = pa0;
        *(uint4*)&sA[arow * 40 + akh + 8] = pa1;
        *(uint4*)&sB[brow * 40 + bkh]     = pb;
        __syncthreads();
        if (it + 1 < NIT) {
            const __nv_bfloat16* nA = gA + (it + 1) * 32;
            pa0 = *(const uint4*)(nA);
            pa1 = *(const uint4*)(nA + 8);
            pb  = *(const uint4*)(gB + (it + 1) * 32);
        }
        #pragma unroll
        for (int k16 = 0; k16 < 2; k16++) {
            uint32_t af[2][4];
            #pragma unroll
            for (int am = 0; am < 2; am++) {
                uint32_t addr = (uint32_t)__cvta_generic_to_shared(
                    &sA[(wm * 32 + am * 16 + a_r) * 40 + k16 * 16 + a_c]);
                asm volatile("ldmatrix.sync.aligned.m8n8.x4.shared.b16 {%0,%1,%2,%3}, [%4];"
                             : "=r"(af[am][0]), "=r"(af[am][1]), "=r"(af[am][2]), "=r"(af[am][3])
                             : "r"(addr));
            }
            uint32_t bfr[2][4];
            #pragma unroll
            for (int bp = 0; bp < 2; bp++) {
                uint32_t addr = (uint32_t)__cvta_generic_to_shared(
                    &sB[(wn * 32 + bp * 16 + b_r) * 40 + k16 * 16 + b_c]);
                asm volatile("ldmatrix.sync.aligned.m8n8.x4.shared.b16 {%0,%1,%2,%3}, [%4];"
                             : "=r"(bfr[bp][0]), "=r"(bfr[bp][1]), "=r"(bfr[bp][2]), "=r"(bfr[bp][3])
                             : "r"(addr));
            }
            #pragma unroll
            for (int am = 0; am < 2; am++) {
                #pragma unroll
                for (int bt = 0; bt < 4; bt++) {
                    uint32_t b0 = bfr[bt >> 1][2 * (bt & 1)];
                    uint32_t b1 = bfr[bt >> 1][2 * (bt & 1) + 1];
                    asm volatile(
                        "mma.sync.aligned.m16n8k16.row.col.f32.bf16.bf16.f32 "
                        "{%0,%1,%2,%3}, {%4,%5,%6,%7}, {%8,%9}, {%0,%1,%2,%3};"
                        : "+f"(acc[am][bt][0]), "+f"(acc[am][bt][1]),
                          "+f"(acc[am][bt][2]), "+f"(acc[am][bt][3])
                        : "r"(af[am][0]), "r"(af[am][1]), "r"(af[am][2]), "r"(af[am][3]),
                          "r"(b0), "r"(b1));
                }
            }
        }
        __syncthreads();
    }

    const int dr = lane >> 2, dn = (lane & 3) * 2;
    #pragma unroll
    for (int am = 0; am < 2; am++) {
        int mrow = bm + wm * 32 + am * 16;
        #pragma unroll
        for (int bt = 0; bt < 4; bt++) {
            int ncol = bn + wn * 32 + bt * 8 + dn;
            float bb0 = bi1[ncol], bb1 = bi1[ncol + 1];
            g_hidden[(mrow + dr) * 256 + ncol]         = fmaxf(acc[am][bt][0] + bb0, 0.f);
            g_hidden[(mrow + dr) * 256 + ncol + 1]     = fmaxf(acc[am][bt][1] + bb1, 0.f);
            g_hidden[(mrow + dr + 8) * 256 + ncol]     = fmaxf(acc[am][bt][2] + bb0, 0.f);
            g_hidden[(mrow + dr + 8) * 256 + ncol + 1] = fmaxf(acc[am][bt][3] + bb1, 0.f);
        }
    }
}

// ---------------- final: pred = Wi2 @ hidden + bi2 + skip ------------------
__global__ void final_kernel(const float* __restrict__ Wi2,
                             const float* __restrict__ bi2,
                             float* __restrict__ out) {
    int idx = blockIdx.x * 128 + threadIdx.x;
    if (idx >= NQ * 3) return;
    int q = idx / 3, o = idx % 3;
    float acc = bi2[o];
    const float* h = g_hidden + q * 256;
    const float* w = Wi2 + o * 256;
    #pragma unroll 8
    for (int c = 0; c < 256; c++) acc += w[c] * h[c];
    out[idx] = acc + g_skip[idx];
}

// ---------------- launcher -------------------------------------------------
extern "C" void kernel_launch(void* const* d_in, const int* in_sizes, int n_in,
                              void* d_out, int out_size) {
    const float* inp    = (const float*)d_in[0];
    const float* coord  = (const float*)d_in[1];
    const float* cell   = (const float*)d_in[2];
    const float* W_enc  = (const float*)d_in[3];
    const float* b_enc  = (const float*)d_in[4];
    const float* W_ch   = (const float*)d_in[5];
    const float* b_ch   = (const float*)d_in[6];
    const float* W_q    = (const float*)d_in[7];
    const float* b_q    = (const float*)d_in[8];
    const float* W_k    = (const float*)d_in[9];
    const float* b_k    = (const float*)d_in[10];
    const float* W_v    = (const float*)d_in[11];
    const float* b_v    = (const float*)d_in[12];
    const float* W_off1 = (const float*)d_in[13];
    const float* b_off1 = (const float*)d_in[14];
    const float* ln_g   = (const float*)d_in[15];
    const float* ln_b   = (const float*)d_in[16];
    const float* W_off2 = (const float*)d_in[17];
    const float* Wc1    = (const float*)d_in[18];
    const float* bc1    = (const float*)d_in[19];
    const float* Wc2    = (const float*)d_in[20];
    const float* bc2    = (const float*)d_in[21];
    const float* Wi1    = (const float*)d_in[22];
    const float* bi1    = (const float*)d_in[23];
    const float* Wi2    = (const float*)d_in[24];
    const float* bi2    = (const float*)d_in[25];
    float* out = (float*)d_out;

    conv_enc_kernel<<<(64 * NPIX + 255) / 256, 256>>>(inp, W_enc, b_enc);
    prep_wqkv_kernel<<<(3 * 9 * 65536 + 255) / 256, 256>>>(W_q, W_k, W_v);
    pad_wi1_kernel<<<(256 * KP + 255) / 256, 256>>>(Wi1);
    transpose_wc1_kernel<<<(98 * 256 + 255) / 256, 256>>>(Wc1);
    conv_ch_kernel<<<dim3(8, 16), 128>>>(W_ch, b_ch);
    conv_qkv_mma_kernel<<<dim3(32, 4, 3), 256>>>(b_q, b_k, b_v);
    conv_off1_kernel<<<dim3(16, 8, 4), 256>>>(W_off1, b_off1);
    ln_gelu_kernel<<<NPIX, 256>>>(ln_g, ln_b);
    conv_off2_kernel<<<NPIX, 128>>>(W_off2);
    query_kernel<<<NQ, 256>>>(coord, cell, inp, bc1, Wc2, bc2);
    gemm_mma_kernel<<<dim3(32, 4), 256>>>(bi1);
    final_kernel<<<(NQ * 3 + 127) / 128, 128>>>(Wi2, bi2, out);
}

// round 14
// speedup vs baseline: 2.4677x; 1.2597x over previous
#include <cuda_runtime.h>
#include <cuda_bf16.h>
#include <stdint.h>
#include <math.h>

// ---------------- problem constants ----------------
#define NPIX 4096
#define NQ   4096
#define KP   12576   // 12546 padded up to 32*393

// ---------------- scratch (device globals; no allocations) ----------------
__device__ __align__(16) __nv_bfloat16 g_encb[NPIX * 64];   // NHWC bf16 enc
__device__ float g_feat[256 * NPIX];          // NCHW 256x64x64 (for off1 path)
__device__ __align__(16) __nv_bfloat16 g_featb[NPIX * 256]; // NHWC bf16
__device__ float g_fq  [NPIX * 256];          // NHWC
__device__ float g_fk  [NPIX * 256];          // NHWC
__device__ float g_fv  [NPIX * 256];          // NHWC
__device__ float g_o   [NPIX * 256];          // NHWC (grouped conv out)
__device__ float g_actv[NPIX * 256];          // NHWC (LN+GELU out)
__device__ float g_offs[NPIX * 98];           // NHWC
__device__ float g_Wc1T[98 * 256];            // transposed Wc1
__device__ __align__(16) __nv_bfloat16 g_Wchb [9 * 256 * 64];       // per-tap [oc,ic]
__device__ __align__(16) __nv_bfloat16 g_Wqkvb[3 * 9 * 256 * 256];  // per-tap [oc,ic]
__device__ __align__(16) __nv_bfloat16 g_Wi1b[256 * KP];            // bf16 padded Wi1
__device__ __align__(16) __nv_bfloat16 g_featin[(size_t)NQ * KP];   // bf16 feat_in
__device__ float g_hidden[NQ * 256];
__device__ float g_skip [NQ * 3];

// ---------------- helpers --------------------------------------------------
__device__ __forceinline__ void cp16(uint32_t dst, const void* src, int nbytes) {
    asm volatile("cp.async.ca.shared.global [%0], [%1], 16, %2;\n"
                 :: "r"(dst), "l"(src), "r"(nbytes));
}
__device__ __forceinline__ void cp_commit() {
    asm volatile("cp.async.commit_group;\n");
}
__device__ __forceinline__ void cp_wait2() {
    asm volatile("cp.async.wait_group 2;\n");
}
__device__ __forceinline__ uint32_t smem_u32(const void* p) {
    return (uint32_t)__cvta_generic_to_shared(p);
}

// shared MMA tile compute: sA (128x40), sB (64x40), BK=32
__device__ __forceinline__ void mma_tile_compute(
    const __nv_bfloat16* __restrict__ sA, const __nv_bfloat16* __restrict__ sB,
    float acc[2][4][4], int wm, int wn, int a_r, int a_c, int b_r, int b_c) {
    #pragma unroll
    for (int k16 = 0; k16 < 2; k16++) {
        uint32_t af[2][4];
        #pragma unroll
        for (int am = 0; am < 2; am++) {
            uint32_t addr = smem_u32(&sA[(wm * 32 + am * 16 + a_r) * 40 + k16 * 16 + a_c]);
            asm volatile("ldmatrix.sync.aligned.m8n8.x4.shared.b16 {%0,%1,%2,%3}, [%4];"
                         : "=r"(af[am][0]), "=r"(af[am][1]), "=r"(af[am][2]), "=r"(af[am][3])
                         : "r"(addr));
        }
        uint32_t bfr[2][4];
        #pragma unroll
        for (int bp = 0; bp < 2; bp++) {
            uint32_t addr = smem_u32(&sB[(wn * 32 + bp * 16 + b_r) * 40 + k16 * 16 + b_c]);
            asm volatile("ldmatrix.sync.aligned.m8n8.x4.shared.b16 {%0,%1,%2,%3}, [%4];"
                         : "=r"(bfr[bp][0]), "=r"(bfr[bp][1]), "=r"(bfr[bp][2]), "=r"(bfr[bp][3])
                         : "r"(addr));
        }
        #pragma unroll
        for (int am = 0; am < 2; am++) {
            #pragma unroll
            for (int bt = 0; bt < 4; bt++) {
                uint32_t b0 = bfr[bt >> 1][2 * (bt & 1)];
                uint32_t b1 = bfr[bt >> 1][2 * (bt & 1) + 1];
                asm volatile(
                    "mma.sync.aligned.m16n8k16.row.col.f32.bf16.bf16.f32 "
                    "{%0,%1,%2,%3}, {%4,%5,%6,%7}, {%8,%9}, {%0,%1,%2,%3};"
                    : "+f"(acc[am][bt][0]), "+f"(acc[am][bt][1]),
                      "+f"(acc[am][bt][2]), "+f"(acc[am][bt][3])
                    : "r"(af[am][0]), "r"(af[am][1]), "r"(af[am][2]), "r"(af[am][3]),
                      "r"(b0), "r"(b1));
            }
        }
    }
}

// ---------------- conv1: 3->64, 3x3, pad1, ReLU -> NHWC bf16 ---------------
__global__ void conv_enc_kernel(const float* __restrict__ inp,
                                const float* __restrict__ w,
                                const float* __restrict__ b) {
    int idx = blockIdx.x * 256 + threadIdx.x;
    if (idx >= 64 * NPIX) return;
    int oc  = idx >> 12;
    int pix = idx & 4095;
    int y = pix >> 6, x = pix & 63;
    float acc = b[oc];
    #pragma unroll
    for (int ic = 0; ic < 3; ic++) {
        #pragma unroll
        for (int dy = 0; dy < 3; dy++) {
            int yy = y + dy - 1;
            if (yy < 0 || yy > 63) continue;
            #pragma unroll
            for (int dx = 0; dx < 3; dx++) {
                int xx = x + dx - 1;
                if (xx < 0 || xx > 63) continue;
                acc += inp[ic * NPIX + yy * 64 + xx] * w[(oc * 3 + ic) * 9 + dy * 3 + dx];
            }
        }
    }
    g_encb[pix * 64 + oc] = __float2bfloat16(fmaxf(acc, 0.f));
}

// ---------------- weight prep ----------------------------------------------
__global__ void prep_wch_kernel(const float* __restrict__ wch) {
    int idx = blockIdx.x * 256 + threadIdx.x;
    if (idx >= 9 * 16384) return;
    int tap = idx / 16384;
    int r = idx % 16384;
    int oc = r >> 6, ic = r & 63;
    g_Wchb[idx] = __float2bfloat16(wch[(oc * 64 + ic) * 9 + tap]);
}
__global__ void prep_wqkv_kernel(const float* __restrict__ wq,
                                 const float* __restrict__ wk,
                                 const float* __restrict__ wv) {
    int idx = blockIdx.x * 256 + threadIdx.x;
    if (idx >= 3 * 9 * 65536) return;
    int z   = idx / (9 * 65536);
    int rem = idx % (9 * 65536);
    int tap = rem / 65536;
    int r2  = rem % 65536;
    int oc = r2 >> 8, ic = r2 & 255;
    const float* w = (z == 0) ? wq : (z == 1) ? wk : wv;
    g_Wqkvb[idx] = __float2bfloat16(w[(oc * 256 + ic) * 9 + tap]);
}
__global__ void transpose_wc1_kernel(const float* __restrict__ Wc1) {
    int idx = blockIdx.x * 256 + threadIdx.x;
    if (idx >= 98 * 256) return;
    int j = idx / 256, c = idx % 256;
    g_Wc1T[idx] = Wc1[c * 98 + j];
}
__global__ void pad_wi1_kernel(const float* __restrict__ Wi1) {
    int idx = blockIdx.x * 256 + threadIdx.x;
    if (idx >= 256 * KP) return;
    int n = idx / KP, k = idx % KP;
    g_Wi1b[idx] = __float2bfloat16((k < 12546) ? Wi1[n * 12546 + k] : 0.f);
}

// ---------------- conv_ch: 64->256 3x3 as bf16 implicit GEMM MMA -----------
// K = 9 taps x 64 ic = 576 -> 18 iters of BK=32; 3-stage cp.async pipeline
__global__ void conv_ch_mma_kernel(const float* __restrict__ bias) {
    __shared__ __align__(16) __nv_bfloat16 sA[3][128 * 40];
    __shared__ __align__(16) __nv_bfloat16 sB[3][64 * 40];
    const int tid  = threadIdx.x;
    const int warp = tid >> 5, lane = tid & 31;
    const int wm = warp & 3, wn = warp >> 2;
    const int bm = blockIdx.x * 128, bn = blockIdx.y * 64;

    float acc[2][4][4];
    #pragma unroll
    for (int i = 0; i < 2; i++)
        #pragma unroll
        for (int j = 0; j < 4; j++)
            #pragma unroll
            for (int r = 0; r < 4; r++) acc[i][j][r] = 0.f;

    const int arow = tid >> 1, akh = (tid & 1) * 16;
    const int brow = tid >> 2, bkh = (tid & 3) * 8;
    const int p   = bm + arow;
    const int pxx = p & 63, pyy = p >> 6;

    const int a_r = ((lane >> 3) & 1) * 8 + (lane & 7);
    const int a_c = (lane >> 4) * 8;
    const int b_r = ((lane >> 4) & 1) * 8 + (lane & 7);
    const int b_c = ((lane >> 3) & 1) * 8;

    auto issue = [&](int it, int st) {
        int tap = it >> 1, kb = it & 1;
        int dy = tap / 3 - 1, dx = tap % 3 - 1;
        bool valid = (pxx + dx >= 0) && (pxx + dx < 64) && (pyy + dy >= 0) && (pyy + dy < 64);
        int pp = valid ? (p + dy * 64 + dx) : p;
        int nb = valid ? 16 : 0;
        const __nv_bfloat16* srcA = g_encb + (size_t)pp * 64 + kb * 32 + akh;
        cp16(smem_u32(&sA[st][arow * 40 + akh]),     srcA,     nb);
        cp16(smem_u32(&sA[st][arow * 40 + akh + 8]), srcA + 8, nb);
        cp16(smem_u32(&sB[st][brow * 40 + bkh]),
             g_Wchb + (size_t)tap * 16384 + (size_t)(bn + brow) * 64 + kb * 32 + bkh, 16);
    };

    const int NIT = 18;
    issue(0, 0); cp_commit();
    issue(1, 1); cp_commit();
    for (int it = 0; it < NIT; it++) {
        int st = it % 3;
        if (it + 2 < NIT) issue(it + 2, (it + 2) % 3);
        cp_commit();
        cp_wait2();
        __syncthreads();
        mma_tile_compute(sA[st], sB[st], acc, wm, wn, a_r, a_c, b_r, b_c);
        __syncthreads();
    }

    const int dr = lane >> 2, dn = (lane & 3) * 2;
    #pragma unroll
    for (int am = 0; am < 2; am++) {
        int mrow = bm + wm * 32 + am * 16;
        #pragma unroll
        for (int bt = 0; bt < 4; bt++) {
            int ncol = bn + wn * 32 + bt * 8 + dn;
            float bb0 = bias[ncol], bb1 = bias[ncol + 1];
            float v00 = acc[am][bt][0] + bb0, v01 = acc[am][bt][1] + bb1;
            float v10 = acc[am][bt][2] + bb0, v11 = acc[am][bt][3] + bb1;
            int p0 = mrow + dr, p1 = mrow + dr + 8;
            g_feat[ncol * NPIX + p0] = v00;  g_feat[(ncol + 1) * NPIX + p0] = v01;
            g_feat[ncol * NPIX + p1] = v10;  g_feat[(ncol + 1) * NPIX + p1] = v11;
            g_featb[p0 * 256 + ncol]     = __float2bfloat16(v00);
            g_featb[p0 * 256 + ncol + 1] = __float2bfloat16(v01);
            g_featb[p1 * 256 + ncol]     = __float2bfloat16(v10);
            g_featb[p1 * 256 + ncol + 1] = __float2bfloat16(v11);
        }
    }
}

// ---------------- qkv convs as bf16 implicit GEMM MMA, 3-stage pipeline ----
__global__ void conv_qkv_mma_kernel(const float* __restrict__ bq,
                                    const float* __restrict__ bk,
                                    const float* __restrict__ bv) {
    __shared__ __align__(16) __nv_bfloat16 sA[3][128 * 40];
    __shared__ __align__(16) __nv_bfloat16 sB[3][64 * 40];
    const int tid  = threadIdx.x;
    const int warp = tid >> 5, lane = tid & 31;
    const int wm = warp & 3, wn = warp >> 2;
    const int bm = blockIdx.x * 128, bn = blockIdx.y * 64;
    const int z = blockIdx.z;
    const float* bias = (z == 0) ? bq : (z == 1) ? bk : bv;
    float* out = (z == 0) ? g_fq : (z == 1) ? g_fk : g_fv;
    const __nv_bfloat16* wbase = g_Wqkvb + (size_t)z * 9 * 65536;

    float acc[2][4][4];
    #pragma unroll
    for (int i = 0; i < 2; i++)
        #pragma unroll
        for (int j = 0; j < 4; j++)
            #pragma unroll
            for (int r = 0; r < 4; r++) acc[i][j][r] = 0.f;

    const int arow = tid >> 1, akh = (tid & 1) * 16;
    const int brow = tid >> 2, bkh = (tid & 3) * 8;
    const int p   = bm + arow;
    const int pxx = p & 63, pyy = p >> 6;

    const int a_r = ((lane >> 3) & 1) * 8 + (lane & 7);
    const int a_c = (lane >> 4) * 8;
    const int b_r = ((lane >> 4) & 1) * 8 + (lane & 7);
    const int b_c = ((lane >> 3) & 1) * 8;

    auto issue = [&](int it, int st) {
        int tap = it >> 3, kb = it & 7;
        int dy = tap / 3 - 1, dx = tap % 3 - 1;
        bool valid = (pxx + dx >= 0) && (pxx + dx < 64) && (pyy + dy >= 0) && (pyy + dy < 64);
        int pp = valid ? (p + dy * 64 + dx) : p;
        int nb = valid ? 16 : 0;
        const __nv_bfloat16* srcA = g_featb + (size_t)pp * 256 + kb * 32 + akh;
        cp16(smem_u32(&sA[st][arow * 40 + akh]),     srcA,     nb);
        cp16(smem_u32(&sA[st][arow * 40 + akh + 8]), srcA + 8, nb);
        cp16(smem_u32(&sB[st][brow * 40 + bkh]),
             wbase + (size_t)tap * 65536 + (size_t)(bn + brow) * 256 + kb * 32 + bkh, 16);
    };

    const int NIT = 72;
    issue(0, 0); cp_commit();
    issue(1, 1); cp_commit();
    for (int it = 0; it < NIT; it++) {
        int st = it % 3;
        if (it + 2 < NIT) issue(it + 2, (it + 2) % 3);
        cp_commit();
        cp_wait2();
        __syncthreads();
        mma_tile_compute(sA[st], sB[st], acc, wm, wn, a_r, a_c, b_r, b_c);
        __syncthreads();
    }

    const int dr = lane >> 2, dn = (lane & 3) * 2;
    #pragma unroll
    for (int am = 0; am < 2; am++) {
        int mrow = bm + wm * 32 + am * 16;
        #pragma unroll
        for (int bt = 0; bt < 4; bt++) {
            int ncol = bn + wn * 32 + bt * 8 + dn;
            float bb0 = bias[ncol], bb1 = bias[ncol + 1];
            out[(mrow + dr) * 256 + ncol]         = acc[am][bt][0] + bb0;
            out[(mrow + dr) * 256 + ncol + 1]     = acc[am][bt][1] + bb1;
            out[(mrow + dr + 8) * 256 + ncol]     = acc[am][bt][2] + bb0;
            out[(mrow + dr + 8) * 256 + ncol + 1] = acc[am][bt][3] + bb1;
        }
    }
}

// ---------------- grouped 5x5 conv (8 groups of 32->32), pad2 --------------
__global__ void conv_off1_kernel(const float* __restrict__ w, const float* __restrict__ bias) {
    const int g = blockIdx.y;
    const int oc0 = blockIdx.z * 8;
    const int tile = blockIdx.x;
    const int x0 = (tile & 3) * 16, y0 = (tile >> 2) * 16;
    const int tid = threadIdx.x;
    const int lx = tid & 15, ly = tid >> 4;
    const int x = x0 + lx, y = y0 + ly;
    __shared__ float sIn[20][20];
    __shared__ float sW[200];
    float acc[8];
    #pragma unroll
    for (int i = 0; i < 8; i++) acc[i] = 0.f;

    for (int ic = 0; ic < 32; ic++) {
        for (int idx = tid; idx < 400; idx += 256) {
            int row = idx / 20, col = idx % 20;
            int gy = y0 + row - 2, gx = x0 + col - 2;
            float v = 0.f;
            if (gy >= 0 && gy < 64 && gx >= 0 && gx < 64)
                v = g_feat[(g * 32 + ic) * NPIX + gy * 64 + gx];
            sIn[row][col] = v;
        }
        if (tid < 200) {
            int oc = tid / 25, pp = tid % 25;
            sW[tid] = w[((g * 32 + oc0 + oc) * 32 + ic) * 25 + pp];
        }
        __syncthreads();
        float r[25];
        #pragma unroll
        for (int pp = 0; pp < 25; pp++) r[pp] = sIn[ly + pp / 5][lx + pp % 5];
        #pragma unroll
        for (int oc = 0; oc < 8; oc++) {
            float a = acc[oc];
            #pragma unroll
            for (int pp = 0; pp < 25; pp++) a += sW[oc * 25 + pp] * r[pp];
            acc[oc] = a;
        }
        __syncthreads();
    }
    #pragma unroll
    for (int oc = 0; oc < 8; oc++)
        g_o[(y * 64 + x) * 256 + g * 32 + oc0 + oc] = acc[oc] + bias[g * 32 + oc0 + oc];
}

// ---------------- LayerNorm(256 ch) + exact GELU (shuffle reduction) -------
__global__ void ln_gelu_kernel(const float* __restrict__ lng, const float* __restrict__ lnb) {
    const int pix = blockIdx.x;
    const int c = threadIdx.x;
    const int lane = c & 31, warp = c >> 5;
    __shared__ float sp[8];
    float x = g_o[pix * 256 + c];

    float s = x;
    #pragma unroll
    for (int o = 16; o > 0; o >>= 1) s += __shfl_xor_sync(0xffffffffu, s, o);
    if (lane == 0) sp[warp] = s;
    __syncthreads();
    float mu;
    {
        float t = (lane < 8) ? sp[lane] : 0.f;
        #pragma unroll
        for (int o = 4; o > 0; o >>= 1) t += __shfl_xor_sync(0xffffffffu, t, o);
        mu = __shfl_sync(0xffffffffu, t, 0) / 256.f;
    }
    float d = x - mu;
    float v = d * d;
    #pragma unroll
    for (int o = 16; o > 0; o >>= 1) v += __shfl_xor_sync(0xffffffffu, v, o);
    __syncthreads();
    if (lane == 0) sp[warp] = v;
    __syncthreads();
    float var;
    {
        float t = (lane < 8) ? sp[lane] : 0.f;
        #pragma unroll
        for (int o = 4; o > 0; o >>= 1) t += __shfl_xor_sync(0xffffffffu, t, o);
        var = __shfl_sync(0xffffffffu, t, 0) / 256.f;
    }
    float xn = d / sqrtf(var + 1e-5f) * lng[c] + lnb[c];
    float ge = 0.5f * xn * (1.0f + erff(xn * 0.7071067811865475f));
    g_actv[pix * 256 + c] = ge;
}

// ---------------- 1x1 conv 256->98, no bias --------------------------------
__global__ void conv_off2_kernel(const float* __restrict__ w) {
    const int pix = blockIdx.x;
    const int tid = threadIdx.x; // 128
    __shared__ float sx[256];
    sx[tid] = g_actv[pix * 256 + tid];
    sx[tid + 128] = g_actv[pix * 256 + tid + 128];
    __syncthreads();
    if (tid < 98) {
        float a = 0.f;
        #pragma unroll 8
        for (int c = 0; c < 256; c++) a += w[tid * 256 + c] * sx[c];
        g_offs[pix * 98 + tid] = a;
    }
}

// ---------------- per-query deformable attention ---------------------------
__global__ void query_kernel(const float* __restrict__ coord,
                             const float* __restrict__ cell,
                             const float* __restrict__ inp,
                             const float* __restrict__ bc1,
                             const float* __restrict__ Wc2,
                             const float* __restrict__ bc2) {
    const int q = blockIdx.x;
    const int tid = threadIdx.x;     // 256
    const int lane = tid & 31;
    const int head = tid >> 5;

    __shared__ int   s_pix[49];
    __shared__ float s_mask[49];
    __shared__ float s_rel[98];
    __shared__ float s_logit[49 * 8];
    __shared__ float s_hid[256];
    __shared__ float s_wc[49];

    const float cy = coord[2 * q], cx = coord[2 * q + 1];
    const float gqx = ((cx + 1.f) * 64.f - 1.f) * 0.5f;
    const float gqy = ((cy + 1.f) * 64.f - 1.f) * 0.5f;
    const float rx = rintf(gqx), ry = rintf(gqy);
    const bool m0 = (rx >= 0.f) && (rx < 64.f) && (ry >= 0.f) && (ry < 64.f);
    const float m0f = m0 ? 1.f : 0.f;
    const int ixq = min(max((int)rx, 0), 63);
    const int iyq = min(max((int)ry, 0), 63);
    const float sck_y = m0f * (-1.f + 1.f / 64.f + (2.f / 64.f) * (float)iyq);
    const float sck_x = m0f * (-1.f + 1.f / 64.f + (2.f / 64.f) * (float)ixq);

    if (tid < 49) {
        int k = tid;
        float o0 = g_offs[(iyq * 64 + ixq) * 98 + 2 * k]     * m0f;
        float o1 = g_offs[(iyq * 64 + ixq) * 98 + 2 * k + 1] * m0f;
        float offy = tanhf(o0) * (2.f / 63.f);
        float offx = tanhf(o1) * (2.f / 63.f);
        float dy = (float)(k / 7 - 3) * (2.f / 64.f);
        float dx = (float)(k % 7 - 3) * (2.f / 64.f);
        float py = sck_y + dy + offy;
        float px = sck_x + dx + offx;
        float gxk = ((px + 1.f) * 64.f - 1.f) * 0.5f;
        float gyk = ((py + 1.f) * 64.f - 1.f) * 0.5f;
        float rxk = rintf(gxk), ryk = rintf(gyk);
        bool mk = (rxk >= 0.f) && (rxk < 64.f) && (ryk >= 0.f) && (ryk < 64.f);
        s_pix[k]  = min(max((int)ryk, 0), 63) * 64 + min(max((int)rxk, 0), 63);
        s_mask[k] = mk ? 1.f : 0.f;
        s_rel[2 * k]     = (cy - py) * 64.f;
        s_rel[2 * k + 1] = (cx - px) * 64.f;
    }
    __syncthreads();

    // q: bilinear zeros-padding sample of fq (per channel = tid)
    float x0f = floorf(gqx), y0f = floorf(gqy);
    float wx = gqx - x0f, wy = gqy - y0f;
    int x0 = (int)x0f, y0 = (int)y0f;
    float qv = 0.f;
    #pragma unroll
    for (int dyc = 0; dyc < 2; dyc++) {
        #pragma unroll
        for (int dxc = 0; dxc < 2; dxc++) {
            int xi = x0 + dxc, yi = y0 + dyc;
            float wgt = (dxc ? wx : 1.f - wx) * (dyc ? wy : 1.f - wy);
            if (xi >= 0 && xi < 64 && yi >= 0 && yi < 64)
                qv += wgt * g_fq[(yi * 64 + xi) * 256 + tid];
        }
    }

    // attention logits
    for (int k = 0; k < 49; k++) {
        float kv = s_mask[k] * g_fk[s_pix[k] * 256 + tid];
        float p = qv * kv;
        p += __shfl_xor_sync(0xffffffffu, p, 16);
        p += __shfl_xor_sync(0xffffffffu, p, 8);
        p += __shfl_xor_sync(0xffffffffu, p, 4);
        p += __shfl_xor_sync(0xffffffffu, p, 2);
        p += __shfl_xor_sync(0xffffffffu, p, 1);
        if (lane == 0) s_logit[k * 8 + head] = p * 0.17677669529663687f;
    }
    __syncthreads();

    // wcoord MLP: 98 -> 256 (relu) -> 49
    {
        float h = bc1[tid];
        #pragma unroll 7
        for (int j = 0; j < 98; j++) h += g_Wc1T[j * 256 + tid] * s_rel[j];
        s_hid[tid] = fmaxf(h, 0.f);
    }
    __syncthreads();
    if (tid < 49) {
        float a = bc2[tid];
        #pragma unroll 8
        for (int c = 0; c < 256; c++) a += Wc2[tid * 256 + c] * s_hid[c];
        s_wc[tid] = a;
    }
    __syncthreads();

    // softmax over k per head
    if (tid < 8) {
        int hh = tid;
        float mx = -1e30f;
        for (int k = 0; k < 49; k++) {
            float t = s_wc[k] + s_logit[k * 8 + hh];
            if (t > mx) mx = t;
        }
        float sum = 0.f;
        for (int k = 0; k < 49; k++) {
            float e = expf(s_wc[k] + s_logit[k * 8 + hh] - mx);
            s_logit[k * 8 + hh] = e;
            sum += e;
        }
        float inv = 1.f / sum;
        for (int k = 0; k < 49; k++) s_logit[k * 8 + hh] *= inv;
    }
    __syncthreads();

    // feat_in = v * attn -> bf16
    size_t base = (size_t)q * KP;
    for (int k = 0; k < 49; k++) {
        float v = s_mask[k] * g_fv[s_pix[k] * 256 + tid];
        g_featin[base + k * 256 + tid] = __float2bfloat16(v * s_logit[k * 8 + head]);
    }
    if (tid < 32) {
        float val = 0.f;
        if (tid == 0) val = cell[2 * q] * 64.f;
        else if (tid == 1) val = cell[2 * q + 1] * 64.f;
        g_featin[base + 12544 + tid] = __float2bfloat16(val);
    }

    // skip: bilinear border sample of inp
    if (tid < 3) {
        float gxc = fminf(fmaxf(gqx, 0.f), 63.f);
        float gyc = fminf(fmaxf(gqy, 0.f), 63.f);
        float xf = floorf(gxc), yf = floorf(gyc);
        float bx = gxc - xf, by = gyc - yf;
        int xa = (int)xf, ya = (int)yf;
        int xb = min(xa + 1, 63), yb = min(ya + 1, 63);
        const float* ch = inp + tid * NPIX;
        float s = (1.f - bx) * (1.f - by) * ch[ya * 64 + xa]
                +        bx  * (1.f - by) * ch[ya * 64 + xb]
                + (1.f - bx) *        by  * ch[yb * 64 + xa]
                +        bx  *        by  * ch[yb * 64 + xb];
        g_skip[q * 3 + tid] = s;
    }
}

// ---------------- GEMM: hidden = relu(feat_in @ Wi1^T + b), 3-stage pipe ---
__global__ void gemm_mma_kernel(const float* __restrict__ bi1) {
    __shared__ __align__(16) __nv_bfloat16 sA[3][128 * 40];
    __shared__ __align__(16) __nv_bfloat16 sB[3][64 * 40];
    const int tid  = threadIdx.x;
    const int warp = tid >> 5, lane = tid & 31;
    const int wm = warp & 3, wn = warp >> 2;
    const int bm = blockIdx.x * 128, bn = blockIdx.y * 64;

    float acc[2][4][4];
    #pragma unroll
    for (int i = 0; i < 2; i++)
        #pragma unroll
        for (int j = 0; j < 4; j++)
            #pragma unroll
            for (int r = 0; r < 4; r++) acc[i][j][r] = 0.f;

    const int arow = tid >> 1, akh = (tid & 1) * 16;
    const int brow = tid >> 2, bkh = (tid & 3) * 8;
    const __nv_bfloat16* gA = g_featin + (size_t)(bm + arow) * KP + akh;
    const __nv_bfloat16* gB = g_Wi1b   + (size_t)(bn + brow) * KP + bkh;

    const int a_r = ((lane >> 3) & 1) * 8 + (lane & 7);
    const int a_c = (lane >> 4) * 8;
    const int b_r = ((lane >> 4) & 1) * 8 + (lane & 7);
    const int b_c = ((lane >> 3) & 1) * 8;

    auto issue = [&](int it, int st) {
        cp16(smem_u32(&sA[st][arow * 40 + akh]),     gA + it * 32,     16);
        cp16(smem_u32(&sA[st][arow * 40 + akh + 8]), gA + it * 32 + 8, 16);
        cp16(smem_u32(&sB[st][brow * 40 + bkh]),     gB + it * 32,     16);
    };

    const int NIT = KP / 32;  // 393
    issue(0, 0); cp_commit();
    issue(1, 1); cp_commit();
    for (int it = 0; it < NIT; it++) {
        int st = it % 3;
        if (it + 2 < NIT) issue(it + 2, (it + 2) % 3);
        cp_commit();
        cp_wait2();
        __syncthreads();
        mma_tile_compute(sA[st], sB[st], acc, wm, wn, a_r, a_c, b_r, b_c);
        __syncthreads();
    }

    const int dr = lane >> 2, dn = (lane & 3) * 2;
    #pragma unroll
    for (int am = 0; am < 2; am++) {
        int mrow = bm + wm * 32 + am * 16;
        #pragma unroll
        for (int bt = 0; bt < 4; bt++) {
            int ncol = bn + wn * 32 + bt * 8 + dn;
            float bb0 = bi1[ncol], bb1 = bi1[ncol + 1];
            g_hidden[(mrow + dr) * 256 + ncol]         = fmaxf(acc[am][bt][0] + bb0, 0.f);
            g_hidden[(mrow + dr) * 256 + ncol + 1]     = fmaxf(acc[am][bt][1] + bb1, 0.f);
            g_hidden[(mrow + dr + 8) * 256 + ncol]     = fmaxf(acc[am][bt][2] + bb0, 0.f);
            g_hidden[(mrow + dr + 8) * 256 + ncol + 1] = fmaxf(acc[am][bt][3] + bb1, 0.f);
        }
    }
}

// ---------------- final: pred = Wi2 @ hidden + bi2 + skip ------------------
__global__ void final_kernel(const float* __restrict__ Wi2,
                             const float* __restrict__ bi2,
                             float* __restrict__ out) {
    int idx = blockIdx.x * 128 + threadIdx.x;
    if (idx >= NQ * 3) return;
    int q = idx / 3, o = idx % 3;
    float acc = bi2[o];
    const float* h = g_hidden + q * 256;
    const float* w = Wi2 + o * 256;
    #pragma unroll 8
    for (int c = 0; c < 256; c++) acc += w[c] * h[c];
    out[idx] = acc + g_skip[idx];
}

// ---------------- launcher -------------------------------------------------
extern "C" void kernel_launch(void* const* d_in, const int* in_sizes, int n_in,
                              void* d_out, int out_size) {
    const float* inp    = (const float*)d_in[0];
    const float* coord  = (const float*)d_in[1];
    const float* cell   = (const float*)d_in[2];
    const float* W_enc  = (const float*)d_in[3];
    const float* b_enc  = (const float*)d_in[4];
    const float* W_ch   = (const float*)d_in[5];
    const float* b_ch   = (const float*)d_in[6];
    const float* W_q    = (const float*)d_in[7];
    const float* b_q    = (const float*)d_in[8];
    const float* W_k    = (const float*)d_in[9];
    const float* b_k    = (const float*)d_in[10];
    const float* W_v    = (const float*)d_in[11];
    const float* b_v    = (const float*)d_in[12];
    const float* W_off1 = (const float*)d_in[13];
    const float* b_off1 = (const float*)d_in[14];
    const float* ln_g   = (const float*)d_in[15];
    const float* ln_b   = (const float*)d_in[16];
    const float* W_off2 = (const float*)d_in[17];
    const float* Wc1    = (const float*)d_in[18];
    const float* bc1    = (const float*)d_in[19];
    const float* Wc2    = (const float*)d_in[20];
    const float* bc2    = (const float*)d_in[21];
    const float* Wi1    = (const float*)d_in[22];
    const float* bi1    = (const float*)d_in[23];
    const float* Wi2    = (const float*)d_in[24];
    const float* bi2    = (const float*)d_in[25];
    float* out = (float*)d_out;

    conv_enc_kernel<<<(64 * NPIX + 255) / 256, 256>>>(inp, W_enc, b_enc);
    prep_wch_kernel<<<(9 * 16384 + 255) / 256, 256>>>(W_ch);
    prep_wqkv_kernel<<<(3 * 9 * 65536 + 255) / 256, 256>>>(W_q, W_k, W_v);
    pad_wi1_kernel<<<(256 * KP + 255) / 256, 256>>>(Wi1);
    transpose_wc1_kernel<<<(98 * 256 + 255) / 256, 256>>>(Wc1);
    conv_ch_mma_kernel<<<dim3(32, 4), 256>>>(b_ch);
    conv_qkv_mma_kernel<<<dim3(32, 4, 3), 256>>>(b_q, b_k, b_v);
    conv_off1_kernel<<<dim3(16, 8, 4), 256>>>(W_off1, b_off1);
    ln_gelu_kernel<<<NPIX, 256>>>(ln_g, ln_b);
    conv_off2_kernel<<<NPIX, 128>>>(W_off2);
    query_kernel<<<NQ, 256>>>(coord, cell, inp, bc1, Wc2, bc2);
    gemm_mma_kernel<<<dim3(32, 4), 256>>>(bi1);
    final_kernel<<<(NQ * 3 + 127) / 128, 128>>>(Wi2, bi2, out);
}